// round 9
// baseline (speedup 1.0000x reference)
#include <cuda_runtime.h>
#include <cuda_fp16.h>
#include <cstdint>

// ---------------- problem constants ----------------
#define NN   4096
#define EE   32768
#define HIDD 128
#define M0   64
#define DIMX 112          // M0 + 3*16
#define WNUM 6400
#define NT   200          // 6400 / 32 column tiles
#define TMB  128          // edges per block
#define NBLK (EE / TMB)   // 256

#define N0C  0.11180339887498948f   // sqrt(1/80)
#define N1C  0.19364916731037085f   // sqrt(3/80)
#define I3C  0.57735026918962576f   // 1/sqrt(3)
#define N1I  (N1C * I3C)

// ---------------- device scratch (no allocation allowed) ----------------
__device__ __half g_Bhi[WNUM * HIDD];   // W2T hi split (fp16), [c][k] k-contiguous
__device__ __half g_Blo[WNUM * HIDD];   // lo split (fp16)
__device__ float g_sums[NN * DIMX];
__device__ float g_cnt[NN];

// ---------------- smem byte layout ----------------
// A plane: 128 rows x 136 halfs (272 B row stride) -> 34816 B (single fp16 plane)
#define SM_A    0
#define SM_B    34816        // 3 bufs x (hi 32x272 + lo 32x272) = 3 x 17408 = 52224
#define SM_B2   87040        // b2: 6400 f32 = 25600 B
#define SM_UN   112640       // union { ea[128][132] f32 (67584) | s/v/p }
#define SM_S    SM_UN                    // 128 x 65 f32
#define SM_V    (SM_UN + 33280)          // 128 x 49 f32
#define SM_P    (SM_UN + 58368)          // 128 x 17 f32
#define SM_SH0  180224       // 128 f32
#define SM_SH1  180736       // 128 x 4 f32
#define SM_TOTAL 182784

// ---------------- helpers ----------------
__device__ __forceinline__ uint32_t smem_u32(const void* p) {
    uint32_t a;
    asm("{ .reg .u64 t; cvta.to.shared.u64 t, %1; cvt.u32.u64 %0, t; }" : "=r"(a) : "l"(p));
    return a;
}
__device__ __forceinline__ void cp16(uint32_t dst, const void* src) {
    asm volatile("cp.async.cg.shared.global [%0], [%1], 16;" :: "r"(dst), "l"(src));
}
#define CP_COMMIT() asm volatile("cp.async.commit_group;" ::: "memory")
#define CP_WAIT1()  asm volatile("cp.async.wait_group 1;" ::: "memory")
#define CP_WAIT0()  asm volatile("cp.async.wait_group 0;" ::: "memory")

__device__ __forceinline__ void ldsm4(uint32_t addr, uint32_t& r0, uint32_t& r1,
                                      uint32_t& r2, uint32_t& r3) {
    asm volatile("ldmatrix.sync.aligned.m8n8.x4.shared.b16 {%0,%1,%2,%3}, [%4];"
                 : "=r"(r0), "=r"(r1), "=r"(r2), "=r"(r3) : "r"(addr));
}
__device__ __forceinline__ void mma16816(float* c, uint32_t a0, uint32_t a1,
                                         uint32_t a2, uint32_t a3,
                                         uint32_t b0, uint32_t b1) {
    asm volatile("mma.sync.aligned.m16n8k16.row.col.f32.f16.f16.f32 "
                 "{%0,%1,%2,%3}, {%4,%5,%6,%7}, {%8,%9}, {%0,%1,%2,%3};"
                 : "+f"(c[0]), "+f"(c[1]), "+f"(c[2]), "+f"(c[3])
                 : "r"(a0), "r"(a1), "r"(a2), "r"(a3), "r"(b0), "r"(b1));
}

// ---------------- prep kernels ----------------
__global__ void zero_kernel() {
    int i = blockIdx.x * blockDim.x + threadIdx.x;
    if (i < NN * DIMX) g_sums[i] = 0.0f;
    if (i < NN)        g_cnt[i]  = 0.0f;
}

// W2 is [HID][WNUM]; build W2T hi/lo fp16 planes [c][k].
__global__ void prep_b(const float* __restrict__ W2) {
    int idx = blockIdx.x * blockDim.x + threadIdx.x;   // c*128 + k
    if (idx >= WNUM * HIDD) return;
    int c = idx >> 7, k = idx & 127;
    float val = W2[(size_t)k * WNUM + c];
    __half hi = __float2half_rn(val);
    g_Bhi[idx] = hi;
    g_Blo[idx] = __float2half_rn(val - __half2float(hi));
}

// Stage B tile t (32 cols x 128 k, hi+lo) into smem buffer slot.
__device__ __forceinline__ void load_b(uint32_t smb, int slot, int t, int tid) {
    uint32_t d = smb + SM_B + (uint32_t)slot * 17408u;
    const char* sH = (const char*)g_Bhi + (size_t)t * 8192;   // 32*128*2
    const char* sL = (const char*)g_Blo + (size_t)t * 8192;
#pragma unroll
    for (int j = 0; j < 2; ++j) {
        int i = j * 256 + tid;           // 0..511 16B chunks
        int row = i >> 4, c = i & 15;
        cp16(d + row * 272 + c * 16, sH + i * 16);
    }
#pragma unroll
    for (int j = 0; j < 2; ++j) {
        int i = j * 256 + tid;
        int row = i >> 4, c = i & 15;
        cp16(d + 8704 + row * 272 + c * 16, sL + i * 16);
    }
}

// ---------------- tile compute + consume (PAR = t&1, compile-time) ----------------
template<int PAR>
__device__ __forceinline__ void tile_step(
    int t, uint32_t aA, uint32_t bA,
    int ea, int ebg, int tg2,
    const float* __restrict__ s_sm, const float* __restrict__ v_sm,
    const float* __restrict__ p_sm, const float* __restrict__ b2s,
    float sh0a, float sh0b,
    float s1a0, float s1a1, float s1a2,
    float s1b0, float s1b1, float s1b2,
    float (&acc0a)[16], float (&acc0b)[16],
    float (&acc1a)[4][3], float (&acc1b)[4][3])
{
    float cf[4][4];
#pragma unroll
    for (int nt = 0; nt < 4; ++nt)
#pragma unroll
        for (int j = 0; j < 4; ++j) cf[nt][j] = 0.f;

#pragma unroll
    for (int kk = 0; kk < 8; ++kk) {
        uint32_t a0, a1, a2, a3;
        ldsm4(aA + kk * 32, a0, a1, a2, a3);
#pragma unroll
        for (int nt = 0; nt < 4; ++nt) {
            uint32_t bh0, bh1, bl0, bl1;
            ldsm4(bA + nt * 2176 + kk * 32, bh0, bh1, bl0, bl1);   // 8*272 = 2176
            mma16816(cf[nt], a0, a1, a2, a3, bh0, bh1);
            mma16816(cf[nt], a0, a1, a2, a3, bl0, bl1);
        }
    }

    // add bias
    float wv[4][4];
    const float* b2t = b2s + t * 32;
#pragma unroll
    for (int nt = 0; nt < 4; ++nt) {
        float b20 = b2t[nt * 8 + tg2];
        float b21 = b2t[nt * 8 + tg2 + 1];
        wv[nt][0] = cf[nt][0] + b20;
        wv[nt][1] = cf[nt][1] + b21;
        wv[nt][2] = cf[nt][2] + b20;
        wv[nt][3] = cf[nt][3] + b21;
    }

    if (t < 128) {                                 // region A: u = t>>1
        int u = t >> 1;
        float lfa = sh0a * s_sm[ea * 65 + u];
        float lfb = sh0b * s_sm[ebg * 65 + u];
#pragma unroll
        for (int nt = 0; nt < 4; ++nt) {
            acc0a[PAR * 8 + nt * 2 + 0] = fmaf(lfa, wv[nt][0], acc0a[PAR * 8 + nt * 2 + 0]);
            acc0a[PAR * 8 + nt * 2 + 1] = fmaf(lfa, wv[nt][1], acc0a[PAR * 8 + nt * 2 + 1]);
            acc0b[PAR * 8 + nt * 2 + 0] = fmaf(lfb, wv[nt][2], acc0b[PAR * 8 + nt * 2 + 0]);
            acc0b[PAR * 8 + nt * 2 + 1] = fmaf(lfb, wv[nt][3], acc0b[PAR * 8 + nt * 2 + 1]);
        }
    } else if (t < 160) {                          // region B
        int tb = 2 * (t - 128);
#pragma unroll
        for (int nt = 0; nt < 4; ++nt) {
            int u = tb + (nt >> 1);
            const int sl = (nt & 1) * 2;
            float sua = s_sm[ea * 65 + u];
            float sub = s_sm[ebg * 65 + u];
            float ta0 = sua * wv[nt][0], ta1 = sua * wv[nt][1];
            float tb0 = sub * wv[nt][2], tb1 = sub * wv[nt][3];
            acc1a[sl + 0][0] = fmaf(ta0, s1a0, acc1a[sl + 0][0]);
            acc1a[sl + 0][1] = fmaf(ta0, s1a1, acc1a[sl + 0][1]);
            acc1a[sl + 0][2] = fmaf(ta0, s1a2, acc1a[sl + 0][2]);
            acc1a[sl + 1][0] = fmaf(ta1, s1a0, acc1a[sl + 1][0]);
            acc1a[sl + 1][1] = fmaf(ta1, s1a1, acc1a[sl + 1][1]);
            acc1a[sl + 1][2] = fmaf(ta1, s1a2, acc1a[sl + 1][2]);
            acc1b[sl + 0][0] = fmaf(tb0, s1b0, acc1b[sl + 0][0]);
            acc1b[sl + 0][1] = fmaf(tb0, s1b1, acc1b[sl + 0][1]);
            acc1b[sl + 0][2] = fmaf(tb0, s1b2, acc1b[sl + 0][2]);
            acc1b[sl + 1][0] = fmaf(tb1, s1b0, acc1b[sl + 1][0]);
            acc1b[sl + 1][1] = fmaf(tb1, s1b1, acc1b[sl + 1][1]);
            acc1b[sl + 1][2] = fmaf(tb1, s1b2, acc1b[sl + 1][2]);
        }
    } else if (t < 168) {                          // region C
        int tb = 2 * (t - 160);
#pragma unroll
        for (int nt = 0; nt < 4; ++nt) {
            int u = tb + (nt >> 1);
            const int sl = (nt & 1) * 2;
            float twa0 = sh0a * wv[nt][0], twa1 = sh0a * wv[nt][1];
            float twb0 = sh0b * wv[nt][2], twb1 = sh0b * wv[nt][3];
            float va0 = v_sm[ea * 49 + u * 3 + 0];
            float va1 = v_sm[ea * 49 + u * 3 + 1];
            float va2 = v_sm[ea * 49 + u * 3 + 2];
            float vb0 = v_sm[ebg * 49 + u * 3 + 0];
            float vb1 = v_sm[ebg * 49 + u * 3 + 1];
            float vb2 = v_sm[ebg * 49 + u * 3 + 2];
            acc1a[sl + 0][0] = fmaf(twa0, va0, acc1a[sl + 0][0]);
            acc1a[sl + 0][1] = fmaf(twa0, va1, acc1a[sl + 0][1]);
            acc1a[sl + 0][2] = fmaf(twa0, va2, acc1a[sl + 0][2]);
            acc1a[sl + 1][0] = fmaf(twa1, va0, acc1a[sl + 1][0]);
            acc1a[sl + 1][1] = fmaf(twa1, va1, acc1a[sl + 1][1]);
            acc1a[sl + 1][2] = fmaf(twa1, va2, acc1a[sl + 1][2]);
            acc1b[sl + 0][0] = fmaf(twb0, vb0, acc1b[sl + 0][0]);
            acc1b[sl + 0][1] = fmaf(twb0, vb1, acc1b[sl + 0][1]);
            acc1b[sl + 0][2] = fmaf(twb0, vb2, acc1b[sl + 0][2]);
            acc1b[sl + 1][0] = fmaf(twb1, vb0, acc1b[sl + 1][0]);
            acc1b[sl + 1][1] = fmaf(twb1, vb1, acc1b[sl + 1][1]);
            acc1b[sl + 1][2] = fmaf(twb1, vb2, acc1b[sl + 1][2]);
        }
    } else {                                       // region D: u = (t-168)>>1
        int u = (t - 168) >> 1;
        float lfa = p_sm[ea * 17 + u];
        float lfb = p_sm[ebg * 17 + u];
#pragma unroll
        for (int nt = 0; nt < 4; ++nt) {
            acc0a[PAR * 8 + nt * 2 + 0] = fmaf(lfa, wv[nt][0], acc0a[PAR * 8 + nt * 2 + 0]);
            acc0a[PAR * 8 + nt * 2 + 1] = fmaf(lfa, wv[nt][1], acc0a[PAR * 8 + nt * 2 + 1]);
            acc0b[PAR * 8 + nt * 2 + 0] = fmaf(lfb, wv[nt][2], acc0b[PAR * 8 + nt * 2 + 0]);
            acc0b[PAR * 8 + nt * 2 + 1] = fmaf(lfb, wv[nt][3], acc0b[PAR * 8 + nt * 2 + 1]);
        }
    }
}

// ---------------- main fused kernel ----------------
__global__ __launch_bounds__(256, 1)
void tp_main(const float* __restrict__ node_attr,
             const int*   __restrict__ edge_index,
             const float* __restrict__ edge_attr,
             const float* __restrict__ edge_sh,
             const float* __restrict__ W1,
             const float* __restrict__ b1,
             const float* __restrict__ b2)
{
    extern __shared__ char smc[];
    const uint32_t smb = smem_u32(smc);
    const int tid = threadIdx.x;
    const int e0  = blockIdx.x * TMB;

    float* sh0_s = (float*)(smc + SM_SH0);
    float* sh1_s = (float*)(smc + SM_SH1);
    float* s_sm  = (float*)(smc + SM_S);
    float* v_sm  = (float*)(smc + SM_V);
    float* p_sm  = (float*)(smc + SM_P);
    float* b2s   = (float*)(smc + SM_B2);

    // group0: b2 + B tile 0 ; group1: B tile 1
    for (int i = tid; i < 1600; i += 256)
        cp16(smb + SM_B2 + i * 16, b2 + i * 4);
    load_b(smb, 0, 0, tid);
    CP_COMMIT();
    load_b(smb, 1, 1, tid);
    CP_COMMIT();

    // ---- phase 1: edge_sh + counts ----
    if (tid < TMB) {
        int e = e0 + tid;
        float4 shv = *(const float4*)(edge_sh + (size_t)e * 4);
        sh0_s[tid] = shv.x;
        sh1_s[tid * 4 + 0] = shv.y;
        sh1_s[tid * 4 + 1] = shv.z;
        sh1_s[tid * 4 + 2] = shv.w;
        atomicAdd(&g_cnt[edge_index[e]], 1.0f);
    }

    // ---- phase 2: edge_attr tile -> union region ----
    float* ea_sm = (float*)(smc + SM_UN);
    {
        const float4* src4 = (const float4*)(edge_attr + (size_t)e0 * 128);
        for (int i = tid; i < TMB * 32; i += 256) {
            int e = i >> 5, j4 = i & 31;
            float4 v = src4[i];
            *(float4*)&ea_sm[e * 132 + j4 * 4] = v;
        }
    }
    __syncthreads();

    // ---- phase 3: h = relu(ea@W1+b1) -> single fp16 plane (row-major, 272B stride) ----
    {
        const int cg = tid & 15, eg = tid >> 4;
        const int c0 = cg * 8, eb = eg * 8;
        float acc[8][8];
#pragma unroll
        for (int q = 0; q < 8; ++q)
#pragma unroll
            for (int m = 0; m < 8; ++m) acc[q][m] = 0.f;
#pragma unroll 2
        for (int j = 0; j < 128; ++j) {
            float4 wlo = *(const float4*)(W1 + j * HIDD + c0);
            float4 whi = *(const float4*)(W1 + j * HIDD + c0 + 4);
            float wvv[8] = {wlo.x, wlo.y, wlo.z, wlo.w, whi.x, whi.y, whi.z, whi.w};
#pragma unroll
            for (int q = 0; q < 8; ++q) {
                float a = ea_sm[(eb + q) * 132 + j];
#pragma unroll
                for (int m = 0; m < 8; ++m) acc[q][m] = fmaf(a, wvv[m], acc[q][m]);
            }
        }
#pragma unroll
        for (int q = 0; q < 8; ++q) {
#pragma unroll
            for (int m2 = 0; m2 < 4; ++m2) {
                float v0 = fmaxf(acc[q][m2 * 2 + 0] + b1[c0 + m2 * 2 + 0], 0.f);
                float v1 = fmaxf(acc[q][m2 * 2 + 1] + b1[c0 + m2 * 2 + 1], 0.f);
                __half2 h2 = __floats2half2_rn(v0, v1);
                uint32_t off = (uint32_t)(eb + q) * 272 + (uint32_t)(c0 + m2 * 2) * 2;
                *(__half2*)(smc + SM_A + off) = h2;
            }
        }
    }
    __syncthreads();

    // ---- phase 4: gather node_attr[dst] -> s/v (overwrites ea) ----
    {
        const int el = tid >> 1, r = tid & 1;
        int dstn = edge_index[EE + e0 + el];
        const float4* nb = (const float4*)(node_attr + (size_t)dstn * DIMX);
#pragma unroll
        for (int tt = 0; tt < 14; ++tt) {
            int f4 = r * 14 + tt;
            float4 v = nb[f4];
            int col = f4 * 4;
            if (col < M0) {
                s_sm[el * 65 + col + 0] = v.x; s_sm[el * 65 + col + 1] = v.y;
                s_sm[el * 65 + col + 2] = v.z; s_sm[el * 65 + col + 3] = v.w;
            } else {
                int q = col - M0;
                v_sm[el * 49 + q + 0] = v.x; v_sm[el * 49 + q + 1] = v.y;
                v_sm[el * 49 + q + 2] = v.z; v_sm[el * 49 + q + 3] = v.w;
            }
        }
    }
    __syncthreads();

    // ---- phase 5: p[u] = I3C * (v[u].sh1) ----
    {
        const int el = tid >> 1, r = tid & 1;
        float s1x = sh1_s[el * 4 + 0], s1y = sh1_s[el * 4 + 1], s1z = sh1_s[el * 4 + 2];
#pragma unroll
        for (int q = 0; q < 8; ++q) {
            int u = r * 8 + q;
            float pv = v_sm[el * 49 + u * 3 + 0] * s1x
                     + v_sm[el * 49 + u * 3 + 1] * s1y
                     + v_sm[el * 49 + u * 3 + 2] * s1z;
            p_sm[el * 17 + u] = I3C * pv;
        }
    }
    __syncthreads();

    // ---- tile loop setup ----
    const int lane = tid & 31;
    const int w    = tid >> 5;
    const int g    = lane >> 2;
    const int tg2  = (lane & 3) * 2;
    const int ea   = w * 16 + g;
    const int ebg  = ea + 8;

    uint32_t aA = smb + SM_A
                + (uint32_t)(w * 16 + (lane & 15)) * 272 + (uint32_t)(lane >> 4) * 16;
    uint32_t bOff = (uint32_t)(lane >> 4) * 8704 + (uint32_t)(lane & 7) * 272
                  + (uint32_t)((lane >> 3) & 1) * 16;
    uint32_t bBase = smb + SM_B + bOff;

    const float sh0a = sh0_s[ea],  sh0b = sh0_s[ebg];
    const float s1a0 = sh1_s[ea * 4 + 0], s1a1 = sh1_s[ea * 4 + 1], s1a2 = sh1_s[ea * 4 + 2];
    const float s1b0 = sh1_s[ebg * 4 + 0], s1b1 = sh1_s[ebg * 4 + 1], s1b2 = sh1_s[ebg * 4 + 2];

    float acc0a[16], acc0b[16];
    float acc1a[4][3], acc1b[4][3];
#pragma unroll
    for (int i = 0; i < 16; ++i) { acc0a[i] = 0.f; acc0b[i] = 0.f; }
#pragma unroll
    for (int j = 0; j < 4; ++j)
#pragma unroll
        for (int i = 0; i < 3; ++i) { acc1a[j][i] = 0.f; acc1b[j][i] = 0.f; }

    // ---- tile loop: 3 buffers, prefetch distance 2, ONE barrier per tile ----
    // At tile t: wait own group t, barrier (group t visible to all; everyone
    // finished reading slot used at t-1), issue load t+2 into that slot, compute.
    for (int t2 = 0; t2 < 100; ++t2) {
        int t = 2 * t2;

        CP_WAIT1();
        __syncthreads();
        if (t + 2 < NT) { load_b(smb, (t + 2) % 3, t + 2, tid); CP_COMMIT(); }
        tile_step<0>(t, aA, bBase + (uint32_t)(t % 3) * 17408u, ea, ebg, tg2,
                     s_sm, v_sm, p_sm, b2s,
                     sh0a, sh0b, s1a0, s1a1, s1a2, s1b0, s1b1, s1b2,
                     acc0a, acc0b, acc1a, acc1b);

        int t1 = t + 1;
        if (t1 < NT - 1) CP_WAIT1(); else CP_WAIT0();
        __syncthreads();
        if (t1 + 2 < NT) { load_b(smb, (t1 + 2) % 3, t1 + 2, tid); CP_COMMIT(); }
        tile_step<1>(t1, aA, bBase + (uint32_t)(t1 % 3) * 17408u, ea, ebg, tg2,
                     s_sm, v_sm, p_sm, b2s,
                     sh0a, sh0b, s1a0, s1a1, s1a2, s1b0, s1b1, s1b2,
                     acc0a, acc0b, acc1a, acc1b);
    }

    // ---- epilogue: scatter-add by src ----
    {
        int sa = edge_index[e0 + ea];
        int sb = edge_index[e0 + ebg];
        float* da = g_sums + (size_t)sa * DIMX;
        float* db = g_sums + (size_t)sb * DIMX;
#pragma unroll
        for (int s = 0; s < 16; ++s) {
            int wp = (s >> 3) * 32 + ((s >> 1) & 3) * 8 + tg2 + (s & 1);
            atomicAdd(da + wp, N0C * acc0a[s]);
            atomicAdd(db + wp, N0C * acc0b[s]);
        }
#pragma unroll
        for (int j = 0; j < 4; ++j) {
            int wp = (j >> 1) * 8 + tg2 + (j & 1);
            atomicAdd(da + M0 + wp * 3 + 0, N1I * acc1a[j][0]);
            atomicAdd(da + M0 + wp * 3 + 1, N1I * acc1a[j][1]);
            atomicAdd(da + M0 + wp * 3 + 2, N1I * acc1a[j][2]);
            atomicAdd(db + M0 + wp * 3 + 0, N1I * acc1b[j][0]);
            atomicAdd(db + M0 + wp * 3 + 1, N1I * acc1b[j][1]);
            atomicAdd(db + M0 + wp * 3 + 2, N1I * acc1b[j][2]);
        }
    }
}

__global__ void finalize(const float* __restrict__ node_attr, float* __restrict__ out) {
    int i = blockIdx.x * blockDim.x + threadIdx.x;
    if (i >= NN * DIMX) return;
    int n = i / DIMX;
    float c = fmaxf(g_cnt[n], 1.0f);
    out[i] = g_sums[i] / c + node_attr[i];
}

extern "C" void kernel_launch(void* const* d_in, const int* in_sizes, int n_in,
                              void* d_out, int out_size) {
    const float* node_attr  = (const float*)d_in[0];
    const int*   edge_index = (const int*)  d_in[1];
    const float* edge_attr  = (const float*)d_in[2];
    const float* edge_sh    = (const float*)d_in[3];
    const float* W1         = (const float*)d_in[6];
    const float* b1         = (const float*)d_in[7];
    const float* W2         = (const float*)d_in[8];
    const float* b2         = (const float*)d_in[9];
    float* out = (float*)d_out;

    cudaFuncSetAttribute(tp_main, cudaFuncAttributeMaxDynamicSharedMemorySize, SM_TOTAL);

    zero_kernel<<<(NN * DIMX + 255) / 256, 256>>>();
    prep_b<<<(WNUM * HIDD + 255) / 256, 256>>>(W2);
    tp_main<<<NBLK, 256, SM_TOTAL>>>(node_attr, edge_index, edge_attr,
                                     edge_sh, W1, b1, b2);
    finalize<<<(NN * DIMX + 255) / 256, 256>>>(node_attr, out);
}

// round 10
// speedup vs baseline: 1.5900x; 1.5900x over previous
#include <cuda_runtime.h>
#include <cuda_fp16.h>
#include <cstdint>

// ---------------- problem constants ----------------
#define NN   4096
#define EE   32768
#define HIDD 128
#define M0   64
#define DIMX 112          // M0 + 3*16
#define WNUM 6400
#define NT   200          // 6400 / 32 column tiles
#define NS   100          // super-iterations (tile pairs)
#define TMB  128          // edges per block
#define NBLK (EE / TMB)   // 256

#define N0C  0.11180339887498948f   // sqrt(1/80)
#define N1C  0.19364916731037085f   // sqrt(3/80)
#define I3C  0.57735026918962576f   // 1/sqrt(3)
#define N1I  (N1C * I3C)

// ---------------- device scratch (no allocation allowed) ----------------
__device__ __half g_Bhi[WNUM * HIDD];   // W2T hi split (fp16), [c][k] k-contiguous
__device__ __half g_Blo[WNUM * HIDD];   // lo split (fp16)
__device__ float g_sums[NN * DIMX];
__device__ float g_cnt[NN];

// ---------------- smem byte layout ----------------
// A plane: 128 rows x 136 halfs (272 B row stride) -> 34816 B (single fp16 plane)
#define SM_A    0
#define SM_B    34816        // 4 slots x 17408 (pairs: slots {0,1}, {2,3}) = 69632
#define SM_B2   104448       // b2: 6400 f32 = 25600 B
#define SM_UN   130048       // union { ea[128][132] f32 (67584) | s/v/p }
#define SM_S    SM_UN                    // 128 x 65 f32
#define SM_V    (SM_UN + 33280)          // 128 x 49 f32
#define SM_P    (SM_UN + 58368)          // 128 x 17 f32
#define SM_SH0  197632       // 128 f32
#define SM_SH1  198144       // 128 x 4 f32
#define SM_TOTAL 200192

// ---------------- helpers ----------------
__device__ __forceinline__ uint32_t smem_u32(const void* p) {
    uint32_t a;
    asm("{ .reg .u64 t; cvta.to.shared.u64 t, %1; cvt.u32.u64 %0, t; }" : "=r"(a) : "l"(p));
    return a;
}
__device__ __forceinline__ void cp16(uint32_t dst, const void* src) {
    asm volatile("cp.async.cg.shared.global [%0], [%1], 16;" :: "r"(dst), "l"(src));
}
#define CP_COMMIT() asm volatile("cp.async.commit_group;" ::: "memory")
#define CP_WAIT1()  asm volatile("cp.async.wait_group 1;" ::: "memory")
#define CP_WAIT0()  asm volatile("cp.async.wait_group 0;" ::: "memory")

__device__ __forceinline__ void ldsm4(uint32_t addr, uint32_t& r0, uint32_t& r1,
                                      uint32_t& r2, uint32_t& r3) {
    asm volatile("ldmatrix.sync.aligned.m8n8.x4.shared.b16 {%0,%1,%2,%3}, [%4];"
                 : "=r"(r0), "=r"(r1), "=r"(r2), "=r"(r3) : "r"(addr));
}
__device__ __forceinline__ void mma16816(float* c, uint32_t a0, uint32_t a1,
                                         uint32_t a2, uint32_t a3,
                                         uint32_t b0, uint32_t b1) {
    asm volatile("mma.sync.aligned.m16n8k16.row.col.f32.f16.f16.f32 "
                 "{%0,%1,%2,%3}, {%4,%5,%6,%7}, {%8,%9}, {%0,%1,%2,%3};"
                 : "+f"(c[0]), "+f"(c[1]), "+f"(c[2]), "+f"(c[3])
                 : "r"(a0), "r"(a1), "r"(a2), "r"(a3), "r"(b0), "r"(b1));
}

// ---------------- prep kernels ----------------
__global__ void zero_kernel() {
    int i = blockIdx.x * blockDim.x + threadIdx.x;
    if (i < NN * DIMX) g_sums[i] = 0.0f;
    if (i < NN)        g_cnt[i]  = 0.0f;
}

// W2 is [HID][WNUM]; build W2T hi/lo fp16 planes [c][k].
__global__ void prep_b(const float* __restrict__ W2) {
    int idx = blockIdx.x * blockDim.x + threadIdx.x;   // c*128 + k
    if (idx >= WNUM * HIDD) return;
    int c = idx >> 7, k = idx & 127;
    float val = W2[(size_t)k * WNUM + c];
    __half hi = __float2half_rn(val);
    g_Bhi[idx] = hi;
    g_Blo[idx] = __float2half_rn(val - __half2float(hi));
}

// Stage a tile PAIR (tiles t, t+1) into pair slot p (slots 2p, 2p+1). 512 threads.
__device__ __forceinline__ void load_pair(uint32_t smb, int p, int t, int tid) {
    uint32_t base = smb + SM_B + (uint32_t)p * 34816u;
#pragma unroll
    for (int half = 0; half < 2; ++half) {           // 0: tile t, 1: tile t+1
        uint32_t d = base + (uint32_t)half * 17408u;
        const char* sH = (const char*)g_Bhi + (size_t)(t + half) * 8192;
        const char* sL = (const char*)g_Blo + (size_t)(t + half) * 8192;
        int row = tid >> 4, c = tid & 15;            // 512 chunks, 1 per thread
        cp16(d + row * 272 + c * 16, sH + tid * 16);
        cp16(d + 8704 + row * 272 + c * 16, sL + tid * 16);
    }
}

// ---------------- tile compute + consume ----------------
__device__ __forceinline__ void tile_step(
    int t, uint32_t aA, uint32_t bA,
    int ea, int ebg, int tg2, int wpar,
    const float* __restrict__ s_sm, const float* __restrict__ v_sm,
    const float* __restrict__ p_sm, const float* __restrict__ b2s,
    float sh0a, float sh0b,
    float s1a0, float s1a1, float s1a2,
    float s1b0, float s1b1, float s1b2,
    float (&acc0a)[8], float (&acc0b)[8],
    float (&acc1a)[4][3], float (&acc1b)[4][3])
{
    float cf[4][4];
#pragma unroll
    for (int nt = 0; nt < 4; ++nt)
#pragma unroll
        for (int j = 0; j < 4; ++j) cf[nt][j] = 0.f;

#pragma unroll
    for (int kk = 0; kk < 8; ++kk) {
        uint32_t a0, a1, a2, a3;
        ldsm4(aA + kk * 32, a0, a1, a2, a3);
#pragma unroll
        for (int nt = 0; nt < 4; ++nt) {
            uint32_t bh0, bh1, bl0, bl1;
            ldsm4(bA + nt * 2176 + kk * 32, bh0, bh1, bl0, bl1);   // 8*272 = 2176
            mma16816(cf[nt], a0, a1, a2, a3, bh0, bh1);
            mma16816(cf[nt], a0, a1, a2, a3, bl0, bl1);
        }
    }

    // add bias
    float wv[4][4];
    const float* b2t = b2s + t * 32;
#pragma unroll
    for (int nt = 0; nt < 4; ++nt) {
        float b20 = b2t[nt * 8 + tg2];
        float b21 = b2t[nt * 8 + tg2 + 1];
        wv[nt][0] = cf[nt][0] + b20;
        wv[nt][1] = cf[nt][1] + b21;
        wv[nt][2] = cf[nt][2] + b20;
        wv[nt][3] = cf[nt][3] + b21;
    }

    if (t < 128) {                                 // region A: u = t>>1
        int u = t >> 1;
        float lfa = sh0a * s_sm[ea * 65 + u];
        float lfb = sh0b * s_sm[ebg * 65 + u];
#pragma unroll
        for (int nt = 0; nt < 4; ++nt) {
            acc0a[nt * 2 + 0] = fmaf(lfa, wv[nt][0], acc0a[nt * 2 + 0]);
            acc0a[nt * 2 + 1] = fmaf(lfa, wv[nt][1], acc0a[nt * 2 + 1]);
            acc0b[nt * 2 + 0] = fmaf(lfb, wv[nt][2], acc0b[nt * 2 + 0]);
            acc0b[nt * 2 + 1] = fmaf(lfb, wv[nt][3], acc0b[nt * 2 + 1]);
        }
    } else if (t < 160) {                          // region B
        int tb = 2 * (t - 128);
#pragma unroll
        for (int nt = 0; nt < 4; ++nt) {
            int u = tb + (nt >> 1);
            const int sl = (nt & 1) * 2;
            float sua = s_sm[ea * 65 + u];
            float sub = s_sm[ebg * 65 + u];
            float ta0 = sua * wv[nt][0], ta1 = sua * wv[nt][1];
            float tb0 = sub * wv[nt][2], tb1 = sub * wv[nt][3];
            acc1a[sl + 0][0] = fmaf(ta0, s1a0, acc1a[sl + 0][0]);
            acc1a[sl + 0][1] = fmaf(ta0, s1a1, acc1a[sl + 0][1]);
            acc1a[sl + 0][2] = fmaf(ta0, s1a2, acc1a[sl + 0][2]);
            acc1a[sl + 1][0] = fmaf(ta1, s1a0, acc1a[sl + 1][0]);
            acc1a[sl + 1][1] = fmaf(ta1, s1a1, acc1a[sl + 1][1]);
            acc1a[sl + 1][2] = fmaf(ta1, s1a2, acc1a[sl + 1][2]);
            acc1b[sl + 0][0] = fmaf(tb0, s1b0, acc1b[sl + 0][0]);
            acc1b[sl + 0][1] = fmaf(tb0, s1b1, acc1b[sl + 0][1]);
            acc1b[sl + 0][2] = fmaf(tb0, s1b2, acc1b[sl + 0][2]);
            acc1b[sl + 1][0] = fmaf(tb1, s1b0, acc1b[sl + 1][0]);
            acc1b[sl + 1][1] = fmaf(tb1, s1b1, acc1b[sl + 1][1]);
            acc1b[sl + 1][2] = fmaf(tb1, s1b2, acc1b[sl + 1][2]);
        }
    } else if (t < 168) {                          // region C
        int tb = 2 * (t - 160);
#pragma unroll
        for (int nt = 0; nt < 4; ++nt) {
            int u = tb + (nt >> 1);
            const int sl = (nt & 1) * 2;
            float twa0 = sh0a * wv[nt][0], twa1 = sh0a * wv[nt][1];
            float twb0 = sh0b * wv[nt][2], twb1 = sh0b * wv[nt][3];
            float va0 = v_sm[ea * 49 + u * 3 + 0];
            float va1 = v_sm[ea * 49 + u * 3 + 1];
            float va2 = v_sm[ea * 49 + u * 3 + 2];
            float vb0 = v_sm[ebg * 49 + u * 3 + 0];
            float vb1 = v_sm[ebg * 49 + u * 3 + 1];
            float vb2 = v_sm[ebg * 49 + u * 3 + 2];
            acc1a[sl + 0][0] = fmaf(twa0, va0, acc1a[sl + 0][0]);
            acc1a[sl + 0][1] = fmaf(twa0, va1, acc1a[sl + 0][1]);
            acc1a[sl + 0][2] = fmaf(twa0, va2, acc1a[sl + 0][2]);
            acc1a[sl + 1][0] = fmaf(twa1, va0, acc1a[sl + 1][0]);
            acc1a[sl + 1][1] = fmaf(twa1, va1, acc1a[sl + 1][1]);
            acc1a[sl + 1][2] = fmaf(twa1, va2, acc1a[sl + 1][2]);
            acc1b[sl + 0][0] = fmaf(twb0, vb0, acc1b[sl + 0][0]);
            acc1b[sl + 0][1] = fmaf(twb0, vb1, acc1b[sl + 0][1]);
            acc1b[sl + 0][2] = fmaf(twb0, vb2, acc1b[sl + 0][2]);
            acc1b[sl + 1][0] = fmaf(twb1, vb0, acc1b[sl + 1][0]);
            acc1b[sl + 1][1] = fmaf(twb1, vb1, acc1b[sl + 1][1]);
            acc1b[sl + 1][2] = fmaf(twb1, vb2, acc1b[sl + 1][2]);
        }
    } else {                                       // region D: u = (t-168)>>1
        int u = (t - 168) >> 1;
        float lfa = p_sm[ea * 17 + u];
        float lfb = p_sm[ebg * 17 + u];
#pragma unroll
        for (int nt = 0; nt < 4; ++nt) {
            acc0a[nt * 2 + 0] = fmaf(lfa, wv[nt][0], acc0a[nt * 2 + 0]);
            acc0a[nt * 2 + 1] = fmaf(lfa, wv[nt][1], acc0a[nt * 2 + 1]);
            acc0b[nt * 2 + 0] = fmaf(lfb, wv[nt][2], acc0b[nt * 2 + 0]);
            acc0b[nt * 2 + 1] = fmaf(lfb, wv[nt][3], acc0b[nt * 2 + 1]);
        }
    }
}

// ---------------- main fused kernel ----------------
__global__ __launch_bounds__(512, 1)
void tp_main(const float* __restrict__ node_attr,
             const int*   __restrict__ edge_index,
             const float* __restrict__ edge_attr,
             const float* __restrict__ edge_sh,
             const float* __restrict__ W1,
             const float* __restrict__ b1,
             const float* __restrict__ b2)
{
    extern __shared__ char smc[];
    const uint32_t smb = smem_u32(smc);
    const int tid = threadIdx.x;
    const int e0  = blockIdx.x * TMB;

    float* sh0_s = (float*)(smc + SM_SH0);
    float* sh1_s = (float*)(smc + SM_SH1);
    float* s_sm  = (float*)(smc + SM_S);
    float* v_sm  = (float*)(smc + SM_V);
    float* p_sm  = (float*)(smc + SM_P);
    float* b2s   = (float*)(smc + SM_B2);

    // group0: b2 + pair0 (tiles 0,1) ; group1: pair1 (tiles 2,3)
    for (int i = tid; i < 1600; i += 512)
        cp16(smb + SM_B2 + i * 16, b2 + i * 4);
    load_pair(smb, 0, 0, tid);
    CP_COMMIT();
    load_pair(smb, 1, 2, tid);
    CP_COMMIT();

    // ---- phase 1: edge_sh + counts ----
    if (tid < TMB) {
        int e = e0 + tid;
        float4 shv = *(const float4*)(edge_sh + (size_t)e * 4);
        sh0_s[tid] = shv.x;
        sh1_s[tid * 4 + 0] = shv.y;
        sh1_s[tid * 4 + 1] = shv.z;
        sh1_s[tid * 4 + 2] = shv.w;
        atomicAdd(&g_cnt[edge_index[e]], 1.0f);
    }

    // ---- phase 2: edge_attr tile -> union region ----
    float* ea_sm = (float*)(smc + SM_UN);
    {
        const float4* src4 = (const float4*)(edge_attr + (size_t)e0 * 128);
        for (int i = tid; i < TMB * 32; i += 512) {
            int e = i >> 5, j4 = i & 31;
            float4 v = src4[i];
            *(float4*)&ea_sm[e * 132 + j4 * 4] = v;
        }
    }
    __syncthreads();

    // ---- phase 3: h = relu(ea@W1+b1) -> single fp16 plane (272B row stride) ----
    {
        const int cg = tid & 15, eg = tid >> 4;    // eg 0..31: 4 edges each
        const int c0 = cg * 8, eb = eg * 4;
        float acc[4][8];
#pragma unroll
        for (int q = 0; q < 4; ++q)
#pragma unroll
            for (int m = 0; m < 8; ++m) acc[q][m] = 0.f;
#pragma unroll 4
        for (int j = 0; j < 128; ++j) {
            float4 wlo = *(const float4*)(W1 + j * HIDD + c0);
            float4 whi = *(const float4*)(W1 + j * HIDD + c0 + 4);
            float wvv[8] = {wlo.x, wlo.y, wlo.z, wlo.w, whi.x, whi.y, whi.z, whi.w};
#pragma unroll
            for (int q = 0; q < 4; ++q) {
                float a = ea_sm[(eb + q) * 132 + j];
#pragma unroll
                for (int m = 0; m < 8; ++m) acc[q][m] = fmaf(a, wvv[m], acc[q][m]);
            }
        }
#pragma unroll
        for (int q = 0; q < 4; ++q) {
#pragma unroll
            for (int m2 = 0; m2 < 4; ++m2) {
                float v0 = fmaxf(acc[q][m2 * 2 + 0] + b1[c0 + m2 * 2 + 0], 0.f);
                float v1 = fmaxf(acc[q][m2 * 2 + 1] + b1[c0 + m2 * 2 + 1], 0.f);
                __half2 h2 = __floats2half2_rn(v0, v1);
                uint32_t off = (uint32_t)(eb + q) * 272 + (uint32_t)(c0 + m2 * 2) * 2;
                *(__half2*)(smc + SM_A + off) = h2;
            }
        }
    }
    __syncthreads();

    // ---- phase 4: gather node_attr[dst] -> s/v (overwrites ea) ----
    {
        const int el = tid >> 2, r = tid & 3;
        int dstn = edge_index[EE + e0 + el];
        const float4* nb = (const float4*)(node_attr + (size_t)dstn * DIMX);
#pragma unroll
        for (int tt = 0; tt < 7; ++tt) {
            int f4 = r * 7 + tt;                    // 0..27
            float4 v = nb[f4];
            int col = f4 * 4;
            if (col < M0) {
                s_sm[el * 65 + col + 0] = v.x; s_sm[el * 65 + col + 1] = v.y;
                s_sm[el * 65 + col + 2] = v.z; s_sm[el * 65 + col + 3] = v.w;
            } else {
                int q = col - M0;
                v_sm[el * 49 + q + 0] = v.x; v_sm[el * 49 + q + 1] = v.y;
                v_sm[el * 49 + q + 2] = v.z; v_sm[el * 49 + q + 3] = v.w;
            }
        }
    }
    __syncthreads();

    // ---- phase 5: p[u] = I3C * (v[u].sh1) ----
    {
        const int el = tid >> 2, r = tid & 3;
        float s1x = sh1_s[el * 4 + 0], s1y = sh1_s[el * 4 + 1], s1z = sh1_s[el * 4 + 2];
#pragma unroll
        for (int q = 0; q < 4; ++q) {
            int u = r * 4 + q;
            float pv = v_sm[el * 49 + u * 3 + 0] * s1x
                     + v_sm[el * 49 + u * 3 + 1] * s1y
                     + v_sm[el * 49 + u * 3 + 2] * s1z;
            p_sm[el * 17 + u] = I3C * pv;
        }
    }
    __syncthreads();

    // ---- tile loop setup ----
    const int lane = tid & 31;
    const int wid  = tid >> 5;       // 0..15
    const int we   = wid & 7;        // edge group
    const int wpar = wid >> 3;       // tile parity handled by this warp
    const int g    = lane >> 2;
    const int tg2  = (lane & 3) * 2;
    const int ea   = we * 16 + g;
    const int ebg  = ea + 8;

    uint32_t aA = smb + SM_A
                + (uint32_t)(we * 16 + (lane & 15)) * 272 + (uint32_t)(lane >> 4) * 16;
    uint32_t bOff = (uint32_t)(lane >> 4) * 8704 + (uint32_t)(lane & 7) * 272
                  + (uint32_t)((lane >> 3) & 1) * 16;
    uint32_t bBase = smb + SM_B + (uint32_t)wpar * 17408u + bOff;

    const float sh0a = sh0_s[ea],  sh0b = sh0_s[ebg];
    const float s1a0 = sh1_s[ea * 4 + 0], s1a1 = sh1_s[ea * 4 + 1], s1a2 = sh1_s[ea * 4 + 2];
    const float s1b0 = sh1_s[ebg * 4 + 0], s1b1 = sh1_s[ebg * 4 + 1], s1b2 = sh1_s[ebg * 4 + 2];

    float acc0a[8], acc0b[8];
    float acc1a[4][3], acc1b[4][3];
#pragma unroll
    for (int i = 0; i < 8; ++i) { acc0a[i] = 0.f; acc0b[i] = 0.f; }
#pragma unroll
    for (int j = 0; j < 4; ++j)
#pragma unroll
        for (int i = 0; i < 3; ++i) { acc1a[j][i] = 0.f; acc1b[j][i] = 0.f; }

    // ---- super-iteration loop: pair s (tiles 2s, 2s+1), R8's proven 2-barrier pattern ----
    for (int s = 0; s < NS; ++s) {
        if (s < NS - 1) CP_WAIT1(); else CP_WAIT0();
        __syncthreads();
        int t = 2 * s + wpar;
        tile_step(t, aA, bBase + (uint32_t)(s & 1) * 34816u, ea, ebg, tg2, wpar,
                  s_sm, v_sm, p_sm, b2s,
                  sh0a, sh0b, s1a0, s1a1, s1a2, s1b0, s1b1, s1b2,
                  acc0a, acc0b, acc1a, acc1b);
        __syncthreads();
        if (s + 2 < NS) { load_pair(smb, s & 1, 2 * s + 4, tid); CP_COMMIT(); }
    }

    // ---- epilogue: scatter-add by src ----
    {
        int sa = edge_index[e0 + ea];
        int sb = edge_index[e0 + ebg];
        float* da = g_sums + (size_t)sa * DIMX;
        float* db = g_sums + (size_t)sb * DIMX;
#pragma unroll
        for (int i = 0; i < 8; ++i) {
            int wp = wpar * 32 + (i >> 1) * 8 + tg2 + (i & 1);
            atomicAdd(da + wp, N0C * acc0a[i]);
            atomicAdd(db + wp, N0C * acc0b[i]);
        }
#pragma unroll
        for (int j = 0; j < 4; ++j) {
            int wp = (j >> 1) * 8 + tg2 + (j & 1);
            atomicAdd(da + M0 + wp * 3 + 0, N1I * acc1a[j][0]);
            atomicAdd(da + M0 + wp * 3 + 1, N1I * acc1a[j][1]);
            atomicAdd(da + M0 + wp * 3 + 2, N1I * acc1a[j][2]);
            atomicAdd(db + M0 + wp * 3 + 0, N1I * acc1b[j][0]);
            atomicAdd(db + M0 + wp * 3 + 1, N1I * acc1b[j][1]);
            atomicAdd(db + M0 + wp * 3 + 2, N1I * acc1b[j][2]);
        }
    }
}

__global__ void finalize(const float* __restrict__ node_attr, float* __restrict__ out) {
    int i = blockIdx.x * blockDim.x + threadIdx.x;
    if (i >= NN * DIMX) return;
    int n = i / DIMX;
    float c = fmaxf(g_cnt[n], 1.0f);
    out[i] = g_sums[i] / c + node_attr[i];
}

extern "C" void kernel_launch(void* const* d_in, const int* in_sizes, int n_in,
                              void* d_out, int out_size) {
    const float* node_attr  = (const float*)d_in[0];
    const int*   edge_index = (const int*)  d_in[1];
    const float* edge_attr  = (const float*)d_in[2];
    const float* edge_sh    = (const float*)d_in[3];
    const float* W1         = (const float*)d_in[6];
    const float* b1         = (const float*)d_in[7];
    const float* W2         = (const float*)d_in[8];
    const float* b2         = (const float*)d_in[9];
    float* out = (float*)d_out;

    cudaFuncSetAttribute(tp_main, cudaFuncAttributeMaxDynamicSharedMemorySize, SM_TOTAL);

    zero_kernel<<<(NN * DIMX + 255) / 256, 256>>>();
    prep_b<<<(WNUM * HIDD + 255) / 256, 256>>>(W2);
    tp_main<<<NBLK, 512, SM_TOTAL>>>(node_attr, edge_index, edge_attr,
                                     edge_sh, W1, b1, b2);
    finalize<<<(NN * DIMX + 255) / 256, 256>>>(node_attr, out);
}

// round 11
// speedup vs baseline: 2.8438x; 1.7886x over previous
#include <cuda_runtime.h>
#include <cuda_fp16.h>
#include <cstdint>

// ---------------- problem constants ----------------
#define NN   4096
#define EE   32768
#define HIDD 128
#define M0   64
#define DIMX 112          // M0 + 3*16
#define WNUM 6400
#define NT   200          // 6400 / 32 column tiles
#define NS   100          // super-iterations (tile pairs)
#define TMB  128          // edges per block
#define NBLK (EE / TMB)   // 256

#define N0C  0.11180339887498948f   // sqrt(1/80)
#define N1C  0.19364916731037085f   // sqrt(3/80)
#define I3C  0.57735026918962576f   // 1/sqrt(3)
#define N1I  (N1C * I3C)

// ---------------- device scratch (no allocation allowed) ----------------
__device__ __half g_B[WNUM * HIDD];    // W2T fp16, [c][k] k-contiguous
__device__ float g_sums[NN * DIMX];
__device__ float g_cnt[NN];

// ---------------- smem byte layout ----------------
// A plane: 128 rows x 136 halfs (272 B row stride) -> 34816 B (single fp16 plane)
// B slot:  32 rows x 272 B = 8704 B (single plane). 4 slots (2 pairs).
#define SM_A    0
#define SM_B    34816        // 4 x 8704 = 34816 -> ends 69632
#define SM_B2   69632        // b2: 6400 f32 = 25600 B
#define SM_UN   95232        // union { ea[128][132] f32 (67584) | s/v/p }
#define SM_S    SM_UN                    // 128 x 65 f32
#define SM_V    (SM_UN + 33280)          // 128 x 49 f32
#define SM_P    (SM_UN + 58368)          // 128 x 17 f32
#define SM_SH0  162816       // 128 f32
#define SM_SH1  163328       // 128 x 4 f32
#define SM_TOTAL 165376

// ---------------- helpers ----------------
__device__ __forceinline__ uint32_t smem_u32(const void* p) {
    uint32_t a;
    asm("{ .reg .u64 t; cvta.to.shared.u64 t, %1; cvt.u32.u64 %0, t; }" : "=r"(a) : "l"(p));
    return a;
}
__device__ __forceinline__ void cp16(uint32_t dst, const void* src) {
    asm volatile("cp.async.cg.shared.global [%0], [%1], 16;" :: "r"(dst), "l"(src));
}
#define CP_COMMIT() asm volatile("cp.async.commit_group;" ::: "memory")
#define CP_WAIT1()  asm volatile("cp.async.wait_group 1;" ::: "memory")
#define CP_WAIT0()  asm volatile("cp.async.wait_group 0;" ::: "memory")

__device__ __forceinline__ void ldsm4(uint32_t addr, uint32_t& r0, uint32_t& r1,
                                      uint32_t& r2, uint32_t& r3) {
    asm volatile("ldmatrix.sync.aligned.m8n8.x4.shared.b16 {%0,%1,%2,%3}, [%4];"
                 : "=r"(r0), "=r"(r1), "=r"(r2), "=r"(r3) : "r"(addr));
}
__device__ __forceinline__ void mma16816(float* c, uint32_t a0, uint32_t a1,
                                         uint32_t a2, uint32_t a3,
                                         uint32_t b0, uint32_t b1) {
    asm volatile("mma.sync.aligned.m16n8k16.row.col.f32.f16.f16.f32 "
                 "{%0,%1,%2,%3}, {%4,%5,%6,%7}, {%8,%9}, {%0,%1,%2,%3};"
                 : "+f"(c[0]), "+f"(c[1]), "+f"(c[2]), "+f"(c[3])
                 : "r"(a0), "r"(a1), "r"(a2), "r"(a3), "r"(b0), "r"(b1));
}

// ---------------- prep kernels ----------------
__global__ void zero_kernel() {
    int i = blockIdx.x * blockDim.x + threadIdx.x;
    if (i < NN * DIMX) g_sums[i] = 0.0f;
    if (i < NN)        g_cnt[i]  = 0.0f;
}

// W2 is [HID][WNUM]; build W2T fp16 plane [c][k].
__global__ void prep_b(const float* __restrict__ W2) {
    int idx = blockIdx.x * blockDim.x + threadIdx.x;   // c*128 + k
    if (idx >= WNUM * HIDD) return;
    int c = idx >> 7, k = idx & 127;
    g_B[idx] = __float2half_rn(W2[(size_t)k * WNUM + c]);
}

// Stage a tile PAIR (tiles t, t+1) into pair slot p (slots 2p, 2p+1). 512 threads.
__device__ __forceinline__ void load_pair(uint32_t smb, int p, int t, int tid) {
    uint32_t base = smb + SM_B + (uint32_t)p * 17408u;
#pragma unroll
    for (int half = 0; half < 2; ++half) {           // 0: tile t, 1: tile t+1
        uint32_t d = base + (uint32_t)half * 8704u;
        const char* src = (const char*)g_B + (size_t)(t + half) * 8192;
        int row = tid >> 4, c = tid & 15;            // 512 chunks, 1 per thread
        cp16(d + row * 272 + c * 16, src + tid * 16);
    }
}

// ---------------- tile compute + consume ----------------
__device__ __forceinline__ void tile_step(
    int t, const uint32_t (&af)[8][4], uint32_t bA,
    int ea, int ebg, int tg2,
    const float* __restrict__ s_sm, const float* __restrict__ v_sm,
    const float* __restrict__ p_sm, const float* __restrict__ b2s,
    float sh0a, float sh0b,
    float s1a0, float s1a1, float s1a2,
    float s1b0, float s1b1, float s1b2,
    float (&acc0a)[8], float (&acc0b)[8],
    float (&acc1a)[4][3], float (&acc1b)[4][3])
{
    float cf[4][4];
#pragma unroll
    for (int nt = 0; nt < 4; ++nt)
#pragma unroll
        for (int j = 0; j < 4; ++j) cf[nt][j] = 0.f;

#pragma unroll
    for (int kk = 0; kk < 8; ++kk) {
#pragma unroll
        for (int nt2 = 0; nt2 < 2; ++nt2) {
            uint32_t b0, b1, b2, b3;
            ldsm4(bA + nt2 * 4352 + kk * 32, b0, b1, b2, b3);   // 16*272 = 4352
            mma16816(cf[nt2 * 2 + 0], af[kk][0], af[kk][1], af[kk][2], af[kk][3], b0, b1);
            mma16816(cf[nt2 * 2 + 1], af[kk][0], af[kk][1], af[kk][2], af[kk][3], b2, b3);
        }
    }

    // add bias
    float wv[4][4];
    const float* b2t = b2s + t * 32;
#pragma unroll
    for (int nt = 0; nt < 4; ++nt) {
        float b20 = b2t[nt * 8 + tg2];
        float b21 = b2t[nt * 8 + tg2 + 1];
        wv[nt][0] = cf[nt][0] + b20;
        wv[nt][1] = cf[nt][1] + b21;
        wv[nt][2] = cf[nt][2] + b20;
        wv[nt][3] = cf[nt][3] + b21;
    }

    if (t < 128) {                                 // region A: u = t>>1
        int u = t >> 1;
        float lfa = sh0a * s_sm[ea * 65 + u];
        float lfb = sh0b * s_sm[ebg * 65 + u];
#pragma unroll
        for (int nt = 0; nt < 4; ++nt) {
            acc0a[nt * 2 + 0] = fmaf(lfa, wv[nt][0], acc0a[nt * 2 + 0]);
            acc0a[nt * 2 + 1] = fmaf(lfa, wv[nt][1], acc0a[nt * 2 + 1]);
            acc0b[nt * 2 + 0] = fmaf(lfb, wv[nt][2], acc0b[nt * 2 + 0]);
            acc0b[nt * 2 + 1] = fmaf(lfb, wv[nt][3], acc0b[nt * 2 + 1]);
        }
    } else if (t < 160) {                          // region B
        int tb = 2 * (t - 128);
#pragma unroll
        for (int nt = 0; nt < 4; ++nt) {
            int u = tb + (nt >> 1);
            const int sl = (nt & 1) * 2;
            float sua = s_sm[ea * 65 + u];
            float sub = s_sm[ebg * 65 + u];
            float ta0 = sua * wv[nt][0], ta1 = sua * wv[nt][1];
            float tb0 = sub * wv[nt][2], tb1 = sub * wv[nt][3];
            acc1a[sl + 0][0] = fmaf(ta0, s1a0, acc1a[sl + 0][0]);
            acc1a[sl + 0][1] = fmaf(ta0, s1a1, acc1a[sl + 0][1]);
            acc1a[sl + 0][2] = fmaf(ta0, s1a2, acc1a[sl + 0][2]);
            acc1a[sl + 1][0] = fmaf(ta1, s1a0, acc1a[sl + 1][0]);
            acc1a[sl + 1][1] = fmaf(ta1, s1a1, acc1a[sl + 1][1]);
            acc1a[sl + 1][2] = fmaf(ta1, s1a2, acc1a[sl + 1][2]);
            acc1b[sl + 0][0] = fmaf(tb0, s1b0, acc1b[sl + 0][0]);
            acc1b[sl + 0][1] = fmaf(tb0, s1b1, acc1b[sl + 0][1]);
            acc1b[sl + 0][2] = fmaf(tb0, s1b2, acc1b[sl + 0][2]);
            acc1b[sl + 1][0] = fmaf(tb1, s1b0, acc1b[sl + 1][0]);
            acc1b[sl + 1][1] = fmaf(tb1, s1b1, acc1b[sl + 1][1]);
            acc1b[sl + 1][2] = fmaf(tb1, s1b2, acc1b[sl + 1][2]);
        }
    } else if (t < 168) {                          // region C
        int tb = 2 * (t - 160);
#pragma unroll
        for (int nt = 0; nt < 4; ++nt) {
            int u = tb + (nt >> 1);
            const int sl = (nt & 1) * 2;
            float twa0 = sh0a * wv[nt][0], twa1 = sh0a * wv[nt][1];
            float twb0 = sh0b * wv[nt][2], twb1 = sh0b * wv[nt][3];
            float va0 = v_sm[ea * 49 + u * 3 + 0];
            float va1 = v_sm[ea * 49 + u * 3 + 1];
            float va2 = v_sm[ea * 49 + u * 3 + 2];
            float vb0 = v_sm[ebg * 49 + u * 3 + 0];
            float vb1 = v_sm[ebg * 49 + u * 3 + 1];
            float vb2 = v_sm[ebg * 49 + u * 3 + 2];
            acc1a[sl + 0][0] = fmaf(twa0, va0, acc1a[sl + 0][0]);
            acc1a[sl + 0][1] = fmaf(twa0, va1, acc1a[sl + 0][1]);
            acc1a[sl + 0][2] = fmaf(twa0, va2, acc1a[sl + 0][2]);
            acc1a[sl + 1][0] = fmaf(twa1, va0, acc1a[sl + 1][0]);
            acc1a[sl + 1][1] = fmaf(twa1, va1, acc1a[sl + 1][1]);
            acc1a[sl + 1][2] = fmaf(twa1, va2, acc1a[sl + 1][2]);
            acc1b[sl + 0][0] = fmaf(twb0, vb0, acc1b[sl + 0][0]);
            acc1b[sl + 0][1] = fmaf(twb0, vb1, acc1b[sl + 0][1]);
            acc1b[sl + 0][2] = fmaf(twb0, vb2, acc1b[sl + 0][2]);
            acc1b[sl + 1][0] = fmaf(twb1, vb0, acc1b[sl + 1][0]);
            acc1b[sl + 1][1] = fmaf(twb1, vb1, acc1b[sl + 1][1]);
            acc1b[sl + 1][2] = fmaf(twb1, vb2, acc1b[sl + 1][2]);
        }
    } else {                                       // region D: u = (t-168)>>1
        int u = (t - 168) >> 1;
        float lfa = p_sm[ea * 17 + u];
        float lfb = p_sm[ebg * 17 + u];
#pragma unroll
        for (int nt = 0; nt < 4; ++nt) {
            acc0a[nt * 2 + 0] = fmaf(lfa, wv[nt][0], acc0a[nt * 2 + 0]);
            acc0a[nt * 2 + 1] = fmaf(lfa, wv[nt][1], acc0a[nt * 2 + 1]);
            acc0b[nt * 2 + 0] = fmaf(lfb, wv[nt][2], acc0b[nt * 2 + 0]);
            acc0b[nt * 2 + 1] = fmaf(lfb, wv[nt][3], acc0b[nt * 2 + 1]);
        }
    }
}

// ---------------- main fused kernel ----------------
__global__ __launch_bounds__(512, 1)
void tp_main(const float* __restrict__ node_attr,
             const int*   __restrict__ edge_index,
             const float* __restrict__ edge_attr,
             const float* __restrict__ edge_sh,
             const float* __restrict__ W1,
             const float* __restrict__ b1,
             const float* __restrict__ b2)
{
    extern __shared__ char smc[];
    const uint32_t smb = smem_u32(smc);
    const int tid = threadIdx.x;
    const int e0  = blockIdx.x * TMB;

    float* sh0_s = (float*)(smc + SM_SH0);
    float* sh1_s = (float*)(smc + SM_SH1);
    float* s_sm  = (float*)(smc + SM_S);
    float* v_sm  = (float*)(smc + SM_V);
    float* p_sm  = (float*)(smc + SM_P);
    float* b2s   = (float*)(smc + SM_B2);

    // group0: b2 + pair0 (tiles 0,1) ; group1: pair1 (tiles 2,3)
    for (int i = tid; i < 1600; i += 512)
        cp16(smb + SM_B2 + i * 16, b2 + i * 4);
    load_pair(smb, 0, 0, tid);
    CP_COMMIT();
    load_pair(smb, 1, 2, tid);
    CP_COMMIT();

    // ---- phase 1: edge_sh + counts ----
    if (tid < TMB) {
        int e = e0 + tid;
        float4 shv = *(const float4*)(edge_sh + (size_t)e * 4);
        sh0_s[tid] = shv.x;
        sh1_s[tid * 4 + 0] = shv.y;
        sh1_s[tid * 4 + 1] = shv.z;
        sh1_s[tid * 4 + 2] = shv.w;
        atomicAdd(&g_cnt[edge_index[e]], 1.0f);
    }

    // ---- phase 2: edge_attr tile -> union region ----
    float* ea_sm = (float*)(smc + SM_UN);
    {
        const float4* src4 = (const float4*)(edge_attr + (size_t)e0 * 128);
        for (int i = tid; i < TMB * 32; i += 512) {
            int e = i >> 5, j4 = i & 31;
            float4 v = src4[i];
            *(float4*)&ea_sm[e * 132 + j4 * 4] = v;
        }
    }
    __syncthreads();

    // ---- phase 3: h = relu(ea@W1+b1) -> single fp16 plane (272B row stride) ----
    {
        const int cg = tid & 15, eg = tid >> 4;    // eg 0..31: 4 edges each
        const int c0 = cg * 8, eb = eg * 4;
        float acc[4][8];
#pragma unroll
        for (int q = 0; q < 4; ++q)
#pragma unroll
            for (int m = 0; m < 8; ++m) acc[q][m] = 0.f;
#pragma unroll 4
        for (int j = 0; j < 128; ++j) {
            float4 wlo = *(const float4*)(W1 + j * HIDD + c0);
            float4 whi = *(const float4*)(W1 + j * HIDD + c0 + 4);
            float wvv[8] = {wlo.x, wlo.y, wlo.z, wlo.w, whi.x, whi.y, whi.z, whi.w};
#pragma unroll
            for (int q = 0; q < 4; ++q) {
                float a = ea_sm[(eb + q) * 132 + j];
#pragma unroll
                for (int m = 0; m < 8; ++m) acc[q][m] = fmaf(a, wvv[m], acc[q][m]);
            }
        }
#pragma unroll
        for (int q = 0; q < 4; ++q) {
#pragma unroll
            for (int m2 = 0; m2 < 4; ++m2) {
                float v0 = fmaxf(acc[q][m2 * 2 + 0] + b1[c0 + m2 * 2 + 0], 0.f);
                float v1 = fmaxf(acc[q][m2 * 2 + 1] + b1[c0 + m2 * 2 + 1], 0.f);
                __half2 h2 = __floats2half2_rn(v0, v1);
                uint32_t off = (uint32_t)(eb + q) * 272 + (uint32_t)(c0 + m2 * 2) * 2;
                *(__half2*)(smc + SM_A + off) = h2;
            }
        }
    }
    __syncthreads();

    // ---- phase 4: gather node_attr[dst] -> s/v (overwrites ea) ----
    {
        const int el = tid >> 2, r = tid & 3;
        int dstn = edge_index[EE + e0 + el];
        const float4* nb = (const float4*)(node_attr + (size_t)dstn * DIMX);
#pragma unroll
        for (int tt = 0; tt < 7; ++tt) {
            int f4 = r * 7 + tt;                    // 0..27
            float4 v = nb[f4];
            int col = f4 * 4;
            if (col < M0) {
                s_sm[el * 65 + col + 0] = v.x; s_sm[el * 65 + col + 1] = v.y;
                s_sm[el * 65 + col + 2] = v.z; s_sm[el * 65 + col + 3] = v.w;
            } else {
                int q = col - M0;
                v_sm[el * 49 + q + 0] = v.x; v_sm[el * 49 + q + 1] = v.y;
                v_sm[el * 49 + q + 2] = v.z; v_sm[el * 49 + q + 3] = v.w;
            }
        }
    }
    __syncthreads();

    // ---- phase 5: p[u] = I3C * (v[u].sh1) ----
    {
        const int el = tid >> 2, r = tid & 3;
        float s1x = sh1_s[el * 4 + 0], s1y = sh1_s[el * 4 + 1], s1z = sh1_s[el * 4 + 2];
#pragma unroll
        for (int q = 0; q < 4; ++q) {
            int u = r * 4 + q;
            float pv = v_sm[el * 49 + u * 3 + 0] * s1x
                     + v_sm[el * 49 + u * 3 + 1] * s1y
                     + v_sm[el * 49 + u * 3 + 2] * s1z;
            p_sm[el * 17 + u] = I3C * pv;
        }
    }
    __syncthreads();

    // ---- tile loop setup ----
    const int lane = tid & 31;
    const int wid  = tid >> 5;       // 0..15
    const int we   = wid & 7;        // edge group
    const int wpar = wid >> 3;       // tile parity handled by this warp
    const int g    = lane >> 2;
    const int tg2  = (lane & 3) * 2;
    const int ea   = we * 16 + g;
    const int ebg  = ea + 8;

    // ---- hoist A fragments (tile-invariant) into registers ----
    uint32_t aA = smb + SM_A
                + (uint32_t)(we * 16 + (lane & 15)) * 272 + (uint32_t)(lane >> 4) * 16;
    uint32_t af[8][4];
#pragma unroll
    for (int kk = 0; kk < 8; ++kk)
        ldsm4(aA + kk * 32, af[kk][0], af[kk][1], af[kk][2], af[kk][3]);

    // B lane addressing (single plane): lanes 0-7: n-sub 0 rows, k+0;
    // 8-15: k+8; 16-23: n-sub 1 rows (+8 rows); 24-31: n-sub 1 k+8.
    uint32_t bOff = (uint32_t)((lane >> 4) & 1) * (8u * 272u)
                  + (uint32_t)(lane & 7) * 272u
                  + (uint32_t)((lane >> 3) & 1) * 16u;
    uint32_t bBase = smb + SM_B + (uint32_t)wpar * 8704u + bOff;

    const float sh0a = sh0_s[ea],  sh0b = sh0_s[ebg];
    const float s1a0 = sh1_s[ea * 4 + 0], s1a1 = sh1_s[ea * 4 + 1], s1a2 = sh1_s[ea * 4 + 2];
    const float s1b0 = sh1_s[ebg * 4 + 0], s1b1 = sh1_s[ebg * 4 + 1], s1b2 = sh1_s[ebg * 4 + 2];

    float acc0a[8], acc0b[8];
    float acc1a[4][3], acc1b[4][3];
#pragma unroll
    for (int i = 0; i < 8; ++i) { acc0a[i] = 0.f; acc0b[i] = 0.f; }
#pragma unroll
    for (int j = 0; j < 4; ++j)
#pragma unroll
        for (int i = 0; i < 3; ++i) { acc1a[j][i] = 0.f; acc1b[j][i] = 0.f; }

    // ---- super-iteration loop: pair s (tiles 2s, 2s+1), 2-barrier double buffer ----
    for (int s = 0; s < NS; ++s) {
        if (s < NS - 1) CP_WAIT1(); else CP_WAIT0();
        __syncthreads();
        int t = 2 * s + wpar;
        tile_step(t, af, bBase + (uint32_t)(s & 1) * 17408u, ea, ebg, tg2,
                  s_sm, v_sm, p_sm, b2s,
                  sh0a, sh0b, s1a0, s1a1, s1a2, s1b0, s1b1, s1b2,
                  acc0a, acc0b, acc1a, acc1b);
        __syncthreads();
        if (s + 2 < NS) { load_pair(smb, s & 1, 2 * s + 4, tid); CP_COMMIT(); }
    }

    // ---- epilogue: scatter-add by src ----
    {
        int sa = edge_index[e0 + ea];
        int sb = edge_index[e0 + ebg];
        float* da = g_sums + (size_t)sa * DIMX;
        float* db = g_sums + (size_t)sb * DIMX;
#pragma unroll
        for (int i = 0; i < 8; ++i) {
            int wp = wpar * 32 + (i >> 1) * 8 + tg2 + (i & 1);
            atomicAdd(da + wp, N0C * acc0a[i]);
            atomicAdd(db + wp, N0C * acc0b[i]);
        }
#pragma unroll
        for (int j = 0; j < 4; ++j) {
            int wp = (j >> 1) * 8 + tg2 + (j & 1);
            atomicAdd(da + M0 + wp * 3 + 0, N1I * acc1a[j][0]);
            atomicAdd(da + M0 + wp * 3 + 1, N1I * acc1a[j][1]);
            atomicAdd(da + M0 + wp * 3 + 2, N1I * acc1a[j][2]);
            atomicAdd(db + M0 + wp * 3 + 0, N1I * acc1b[j][0]);
            atomicAdd(db + M0 + wp * 3 + 1, N1I * acc1b[j][1]);
            atomicAdd(db + M0 + wp * 3 + 2, N1I * acc1b[j][2]);
        }
    }
}

__global__ void finalize(const float* __restrict__ node_attr, float* __restrict__ out) {
    int i = blockIdx.x * blockDim.x + threadIdx.x;
    if (i >= NN * DIMX) return;
    int n = i / DIMX;
    float c = fmaxf(g_cnt[n], 1.0f);
    out[i] = g_sums[i] / c + node_attr[i];
}

extern "C" void kernel_launch(void* const* d_in, const int* in_sizes, int n_in,
                              void* d_out, int out_size) {
    const float* node_attr  = (const float*)d_in[0];
    const int*   edge_index = (const int*)  d_in[1];
    const float* edge_attr  = (const float*)d_in[2];
    const float* edge_sh    = (const float*)d_in[3];
    const float* W1         = (const float*)d_in[6];
    const float* b1         = (const float*)d_in[7];
    const float* W2         = (const float*)d_in[8];
    const float* b2         = (const float*)d_in[9];
    float* out = (float*)d_out;

    cudaFuncSetAttribute(tp_main, cudaFuncAttributeMaxDynamicSharedMemorySize, SM_TOTAL);

    zero_kernel<<<(NN * DIMX + 255) / 256, 256>>>();
    prep_b<<<(WNUM * HIDD + 255) / 256, 256>>>(W2);
    tp_main<<<NBLK, 512, SM_TOTAL>>>(node_attr, edge_index, edge_attr,
                                     edge_sh, W1, b1, b2);
    finalize<<<(NN * DIMX + 255) / 256, 256>>>(node_attr, out);
}

// round 14
// speedup vs baseline: 3.1937x; 1.1230x over previous
#include <cuda_runtime.h>
#include <cuda_fp16.h>
#include <cstdint>

// ---------------- problem constants ----------------
#define NN   4096
#define EE   32768
#define HIDD 128
#define M0   64
#define DIMX 112          // M0 + 3*16
#define WNUM 6400
#define NT   200          // 6400 / 32 column tiles
#define NS   100          // super-iterations (tile pairs)
#define TMB  128          // edges per block
#define NBLK (EE / TMB)   // 256

#define N0C  0.11180339887498948f   // sqrt(1/80)
#define N1C  0.19364916731037085f   // sqrt(3/80)
#define I3C  0.57735026918962576f   // 1/sqrt(3)
#define N1I  (N1C * I3C)

// ---------------- device scratch (no allocation allowed) ----------------
__device__ __half g_B[WNUM * HIDD];     // W2T fp16, [c][k] k-contiguous
__device__ __half g_W1h[HIDD * HIDD];   // W1T fp16, [c][j] j-contiguous
__device__ __half g_EA[EE * 128];       // edge_attr fp16
__device__ float g_sums[NN * DIMX];
__device__ float g_cnt[NN];

// ---------------- smem byte layout ----------------
// A plane: 128 rows x 136 halfs (272 B row stride) -> 34816 B (h fp16)
// B slot:  32 rows x 272 B = 8704 B. 4 slots (2 pairs).
#define SM_A    0
#define SM_B    34816        // 4 x 8704 -> ends 69632
#define SM_B2   69632        // b2: 6400 f32 = 25600 B
#define SM_UN   95232        // union: [ea16 34816 | W1h 34816] then s/v/p
#define SM_W1   (SM_UN + 34816)          // 130048
#define SM_S    SM_UN                    // 128 x 65 f32 (33280)
#define SM_V    (SM_UN + 33280)          // 128 x 49 f32 (25088)
#define SM_P    (SM_UN + 58368)          // 128 x 17 f32 (8704)
#define SM_SH0  164864       // 128 f32
#define SM_SH1  165376       // 128 x 4 f32
#define SM_B1S  167424       // b1: 128 f32
#define SM_TOTAL 167936

// ---------------- helpers ----------------
__device__ __forceinline__ uint32_t smem_u32(const void* p) {
    uint32_t a;
    asm("{ .reg .u64 t; cvta.to.shared.u64 t, %1; cvt.u32.u64 %0, t; }" : "=r"(a) : "l"(p));
    return a;
}
__device__ __forceinline__ void cp16(uint32_t dst, const void* src) {
    asm volatile("cp.async.cg.shared.global [%0], [%1], 16;" :: "r"(dst), "l"(src));
}
#define CP_COMMIT() asm volatile("cp.async.commit_group;" ::: "memory")
#define CP_WAIT2()  asm volatile("cp.async.wait_group 2;" ::: "memory")
#define CP_WAIT1()  asm volatile("cp.async.wait_group 1;" ::: "memory")
#define CP_WAIT0()  asm volatile("cp.async.wait_group 0;" ::: "memory")

__device__ __forceinline__ void ldsm4(uint32_t addr, uint32_t& r0, uint32_t& r1,
                                      uint32_t& r2, uint32_t& r3) {
    asm volatile("ldmatrix.sync.aligned.m8n8.x4.shared.b16 {%0,%1,%2,%3}, [%4];"
                 : "=r"(r0), "=r"(r1), "=r"(r2), "=r"(r3) : "r"(addr));
}
__device__ __forceinline__ void mma16816(float* c, uint32_t a0, uint32_t a1,
                                         uint32_t a2, uint32_t a3,
                                         uint32_t b0, uint32_t b1) {
    asm volatile("mma.sync.aligned.m16n8k16.row.col.f32.f16.f16.f32 "
                 "{%0,%1,%2,%3}, {%4,%5,%6,%7}, {%8,%9}, {%0,%1,%2,%3};"
                 : "+f"(c[0]), "+f"(c[1]), "+f"(c[2]), "+f"(c[3])
                 : "r"(a0), "r"(a1), "r"(a2), "r"(a3), "r"(b0), "r"(b1));
}

// ---------------- single prep kernel (zero + all fp16 conversions) ----------------
__global__ void prep(const float* __restrict__ W2, const float* __restrict__ W1,
                     const float* __restrict__ EA) {
    int idx = blockIdx.x * blockDim.x + threadIdx.x;
    if (idx < EE * 128)
        g_EA[idx] = __float2half_rn(EA[idx]);
    if (idx < WNUM * HIDD) {
        int c = idx >> 7, k = idx & 127;
        g_B[idx] = __float2half_rn(W2[(size_t)k * WNUM + c]);
    }
    if (idx < HIDD * HIDD) {
        int c = idx >> 7, j = idx & 127;
        g_W1h[idx] = __float2half_rn(W1[j * HIDD + c]);
    }
    if (idx < NN * DIMX) g_sums[idx] = 0.0f;
    if (idx < NN)        g_cnt[idx]  = 0.0f;
}

// Stage a tile PAIR (tiles t, t+1) into pair slot p. 512 threads.
__device__ __forceinline__ void load_pair(uint32_t smb, int p, int t, int tid) {
    uint32_t base = smb + SM_B + (uint32_t)p * 17408u;
#pragma unroll
    for (int half = 0; half < 2; ++half) {
        uint32_t d = base + (uint32_t)half * 8704u;
        const char* src = (const char*)g_B + (size_t)(t + half) * 8192;
        int row = tid >> 4, c = tid & 15;
        cp16(d + row * 272 + c * 16, src + tid * 16);
    }
}

// ---------------- tile compute + consume (unchanged from R11) ----------------
__device__ __forceinline__ void tile_step(
    int t, const uint32_t (&af)[8][4], uint32_t bA,
    int ea, int ebg, int tg2,
    const float* __restrict__ s_sm, const float* __restrict__ v_sm,
    const float* __restrict__ p_sm, const float* __restrict__ b2s,
    float sh0a, float sh0b,
    float s1a0, float s1a1, float s1a2,
    float s1b0, float s1b1, float s1b2,
    float (&acc0a)[8], float (&acc0b)[8],
    float (&acc1a)[4][3], float (&acc1b)[4][3])
{
    float cf[4][4];
#pragma unroll
    for (int nt = 0; nt < 4; ++nt)
#pragma unroll
        for (int j = 0; j < 4; ++j) cf[nt][j] = 0.f;

#pragma unroll
    for (int kk = 0; kk < 8; ++kk) {
#pragma unroll
        for (int nt2 = 0; nt2 < 2; ++nt2) {
            uint32_t b0, b1, b2, b3;
            ldsm4(bA + nt2 * 4352 + kk * 32, b0, b1, b2, b3);
            mma16816(cf[nt2 * 2 + 0], af[kk][0], af[kk][1], af[kk][2], af[kk][3], b0, b1);
            mma16816(cf[nt2 * 2 + 1], af[kk][0], af[kk][1], af[kk][2], af[kk][3], b2, b3);
        }
    }

    float wv[4][4];
    const float* b2t = b2s + t * 32;
#pragma unroll
    for (int nt = 0; nt < 4; ++nt) {
        float b20 = b2t[nt * 8 + tg2];
        float b21 = b2t[nt * 8 + tg2 + 1];
        wv[nt][0] = cf[nt][0] + b20;
        wv[nt][1] = cf[nt][1] + b21;
        wv[nt][2] = cf[nt][2] + b20;
        wv[nt][3] = cf[nt][3] + b21;
    }

    if (t < 128) {
        int u = t >> 1;
        float lfa = sh0a * s_sm[ea * 65 + u];
        float lfb = sh0b * s_sm[ebg * 65 + u];
#pragma unroll
        for (int nt = 0; nt < 4; ++nt) {
            acc0a[nt * 2 + 0] = fmaf(lfa, wv[nt][0], acc0a[nt * 2 + 0]);
            acc0a[nt * 2 + 1] = fmaf(lfa, wv[nt][1], acc0a[nt * 2 + 1]);
            acc0b[nt * 2 + 0] = fmaf(lfb, wv[nt][2], acc0b[nt * 2 + 0]);
            acc0b[nt * 2 + 1] = fmaf(lfb, wv[nt][3], acc0b[nt * 2 + 1]);
        }
    } else if (t < 160) {
        int tb = 2 * (t - 128);
#pragma unroll
        for (int nt = 0; nt < 4; ++nt) {
            int u = tb + (nt >> 1);
            const int sl = (nt & 1) * 2;
            float sua = s_sm[ea * 65 + u];
            float sub = s_sm[ebg * 65 + u];
            float ta0 = sua * wv[nt][0], ta1 = sua * wv[nt][1];
            float tb0 = sub * wv[nt][2], tb1 = sub * wv[nt][3];
            acc1a[sl + 0][0] = fmaf(ta0, s1a0, acc1a[sl + 0][0]);
            acc1a[sl + 0][1] = fmaf(ta0, s1a1, acc1a[sl + 0][1]);
            acc1a[sl + 0][2] = fmaf(ta0, s1a2, acc1a[sl + 0][2]);
            acc1a[sl + 1][0] = fmaf(ta1, s1a0, acc1a[sl + 1][0]);
            acc1a[sl + 1][1] = fmaf(ta1, s1a1, acc1a[sl + 1][1]);
            acc1a[sl + 1][2] = fmaf(ta1, s1a2, acc1a[sl + 1][2]);
            acc1b[sl + 0][0] = fmaf(tb0, s1b0, acc1b[sl + 0][0]);
            acc1b[sl + 0][1] = fmaf(tb0, s1b1, acc1b[sl + 0][1]);
            acc1b[sl + 0][2] = fmaf(tb0, s1b2, acc1b[sl + 0][2]);
            acc1b[sl + 1][0] = fmaf(tb1, s1b0, acc1b[sl + 1][0]);
            acc1b[sl + 1][1] = fmaf(tb1, s1b1, acc1b[sl + 1][1]);
            acc1b[sl + 1][2] = fmaf(tb1, s1b2, acc1b[sl + 1][2]);
        }
    } else if (t < 168) {
        int tb = 2 * (t - 160);
#pragma unroll
        for (int nt = 0; nt < 4; ++nt) {
            int u = tb + (nt >> 1);
            const int sl = (nt & 1) * 2;
            float twa0 = sh0a * wv[nt][0], twa1 = sh0a * wv[nt][1];
            float twb0 = sh0b * wv[nt][2], twb1 = sh0b * wv[nt][3];
            float va0 = v_sm[ea * 49 + u * 3 + 0];
            float va1 = v_sm[ea * 49 + u * 3 + 1];
            float va2 = v_sm[ea * 49 + u * 3 + 2];
            float vb0 = v_sm[ebg * 49 + u * 3 + 0];
            float vb1 = v_sm[ebg * 49 + u * 3 + 1];
            float vb2 = v_sm[ebg * 49 + u * 3 + 2];
            acc1a[sl + 0][0] = fmaf(twa0, va0, acc1a[sl + 0][0]);
            acc1a[sl + 0][1] = fmaf(twa0, va1, acc1a[sl + 0][1]);
            acc1a[sl + 0][2] = fmaf(twa0, va2, acc1a[sl + 0][2]);
            acc1a[sl + 1][0] = fmaf(twa1, va0, acc1a[sl + 1][0]);
            acc1a[sl + 1][1] = fmaf(twa1, va1, acc1a[sl + 1][1]);
            acc1a[sl + 1][2] = fmaf(twa1, va2, acc1a[sl + 1][2]);
            acc1b[sl + 0][0] = fmaf(twb0, vb0, acc1b[sl + 0][0]);
            acc1b[sl + 0][1] = fmaf(twb0, vb1, acc1b[sl + 0][1]);
            acc1b[sl + 0][2] = fmaf(twb0, vb2, acc1b[sl + 0][2]);
            acc1b[sl + 1][0] = fmaf(twb1, vb0, acc1b[sl + 1][0]);
            acc1b[sl + 1][1] = fmaf(twb1, vb1, acc1b[sl + 1][1]);
            acc1b[sl + 1][2] = fmaf(twb1, vb2, acc1b[sl + 1][2]);
        }
    } else {
        int u = (t - 168) >> 1;
        float lfa = p_sm[ea * 17 + u];
        float lfb = p_sm[ebg * 17 + u];
#pragma unroll
        for (int nt = 0; nt < 4; ++nt) {
            acc0a[nt * 2 + 0] = fmaf(lfa, wv[nt][0], acc0a[nt * 2 + 0]);
            acc0a[nt * 2 + 1] = fmaf(lfa, wv[nt][1], acc0a[nt * 2 + 1]);
            acc0b[nt * 2 + 0] = fmaf(lfb, wv[nt][2], acc0b[nt * 2 + 0]);
            acc0b[nt * 2 + 1] = fmaf(lfb, wv[nt][3], acc0b[nt * 2 + 1]);
        }
    }
}

// ---------------- main fused kernel ----------------
__global__ __launch_bounds__(512, 1)
void tp_main(const float* __restrict__ node_attr,
             const int*   __restrict__ edge_index,
             const float* __restrict__ edge_attr,
             const float* __restrict__ edge_sh,
             const float* __restrict__ b1,
             const float* __restrict__ b2)
{
    extern __shared__ char smc[];
    const uint32_t smb = smem_u32(smc);
    const int tid = threadIdx.x;
    const int e0  = blockIdx.x * TMB;

    float* sh0_s = (float*)(smc + SM_SH0);
    float* sh1_s = (float*)(smc + SM_SH1);
    float* s_sm  = (float*)(smc + SM_S);
    float* v_sm  = (float*)(smc + SM_V);
    float* p_sm  = (float*)(smc + SM_P);
    float* b2s   = (float*)(smc + SM_B2);
    float* b1s   = (float*)(smc + SM_B1S);

    // ---- lane/warp decomposition (used by phase 3 AND mainloop) ----
    const int lane = tid & 31;
    const int wid  = tid >> 5;       // 0..15
    const int we   = wid & 7;        // edge group
    const int wpar = wid >> 3;       // tile parity / col half
    const int g    = lane >> 2;
    const int tg2  = (lane & 3) * 2;
    const int ea   = we * 16 + g;
    const int ebg  = ea + 8;
    uint32_t bOff = (uint32_t)((lane >> 4) & 1) * (8u * 272u)
                  + (uint32_t)(lane & 7) * 272u
                  + (uint32_t)((lane >> 3) & 1) * 16u;

    // ---- prologue cp.async: g0 = {b2, b1, ea16, W1h}; g1 = pair0; g2 = pair1 ----
    for (int i = tid; i < 1600; i += 512)
        cp16(smb + SM_B2 + i * 16, b2 + i * 4);
    if (tid < 32)
        cp16(smb + SM_B1S + tid * 16, b1 + tid * 4);
#pragma unroll
    for (int j = 0; j < 4; ++j) {                   // ea16: 2048 chunks
        int i = j * 512 + tid;
        int row = i >> 4, c = i & 15;
        cp16(smb + SM_UN + row * 272 + c * 16,
             (const char*)g_EA + (size_t)e0 * 256 + (size_t)i * 16);
    }
#pragma unroll
    for (int j = 0; j < 4; ++j) {                   // W1h: 2048 chunks
        int i = j * 512 + tid;
        int row = i >> 4, c = i & 15;
        cp16(smb + SM_W1 + row * 272 + c * 16, (const char*)g_W1h + (size_t)i * 16);
    }
    CP_COMMIT();
    load_pair(smb, 0, 0, tid);
    CP_COMMIT();
    load_pair(smb, 1, 2, tid);
    CP_COMMIT();

    // ---- phase 1: edge_sh + counts ----
    if (tid < TMB) {
        int e = e0 + tid;
        float4 shv = *(const float4*)(edge_sh + (size_t)e * 4);
        sh0_s[tid] = shv.x;
        sh1_s[tid * 4 + 0] = shv.y;
        sh1_s[tid * 4 + 1] = shv.z;
        sh1_s[tid * 4 + 2] = shv.w;
        atomicAdd(&g_cnt[edge_index[e]], 1.0f);
    }

    CP_WAIT2();            // g0 (b2,b1,ea16,W1h) complete
    __syncthreads();

    // ---- phase 3: h = relu(ea@W1+b1) via MMA -> fp16 A plane ----
    {
        uint32_t aE = smb + SM_UN
                    + (uint32_t)(we * 16 + (lane & 15)) * 272 + (uint32_t)(lane >> 4) * 16;
        uint32_t ef[8][4];
#pragma unroll
        for (int kk = 0; kk < 8; ++kk)
            ldsm4(aE + kk * 32, ef[kk][0], ef[kk][1], ef[kk][2], ef[kk][3]);

        uint32_t bW = smb + SM_W1 + (uint32_t)wpar * (64u * 272u) + bOff;
#pragma unroll
        for (int grp = 0; grp < 2; ++grp) {
            float cf[4][4];
#pragma unroll
            for (int nt = 0; nt < 4; ++nt)
#pragma unroll
                for (int j = 0; j < 4; ++j) cf[nt][j] = 0.f;
#pragma unroll
            for (int kk = 0; kk < 8; ++kk) {
#pragma unroll
                for (int nt2 = 0; nt2 < 2; ++nt2) {
                    uint32_t b0, b1r, b2r, b3;
                    ldsm4(bW + grp * (32u * 272u) + nt2 * 4352 + kk * 32, b0, b1r, b2r, b3);
                    mma16816(cf[nt2 * 2 + 0], ef[kk][0], ef[kk][1], ef[kk][2], ef[kk][3], b0, b1r);
                    mma16816(cf[nt2 * 2 + 1], ef[kk][0], ef[kk][1], ef[kk][2], ef[kk][3], b2r, b3);
                }
            }
            int c0b = wpar * 64 + grp * 32;
#pragma unroll
            for (int nt = 0; nt < 4; ++nt) {
                int c0 = c0b + nt * 8 + tg2;
                float bb0 = b1s[c0], bb1 = b1s[c0 + 1];
                __half2 h0 = __floats2half2_rn(fmaxf(cf[nt][0] + bb0, 0.f),
                                               fmaxf(cf[nt][1] + bb1, 0.f));
                __half2 h1 = __floats2half2_rn(fmaxf(cf[nt][2] + bb0, 0.f),
                                               fmaxf(cf[nt][3] + bb1, 0.f));
                *(__half2*)(smc + SM_A + (we * 16 + g) * 272 + c0 * 2) = h0;
                *(__half2*)(smc + SM_A + (we * 16 + g + 8) * 272 + c0 * 2) = h1;
            }
        }
    }
    __syncthreads();   // phase-3 reads of ea16/W1h done; h stores visible

    // ---- phase 4: gather node_attr[dst] -> s/v (overwrites ea16/W1h) ----
    {
        const int el = tid >> 2, r = tid & 3;
        int dstn = edge_index[EE + e0 + el];
        const float4* nb = (const float4*)(node_attr + (size_t)dstn * DIMX);
#pragma unroll
        for (int tt = 0; tt < 7; ++tt) {
            int f4 = r * 7 + tt;
            float4 v = nb[f4];
            int col = f4 * 4;
            if (col < M0) {
                s_sm[el * 65 + col + 0] = v.x; s_sm[el * 65 + col + 1] = v.y;
                s_sm[el * 65 + col + 2] = v.z; s_sm[el * 65 + col + 3] = v.w;
            } else {
                int q = col - M0;
                v_sm[el * 49 + q + 0] = v.x; v_sm[el * 49 + q + 1] = v.y;
                v_sm[el * 49 + q + 2] = v.z; v_sm[el * 49 + q + 3] = v.w;
            }
        }
    }
    __syncthreads();

    // ---- phase 5: p[u] = I3C * (v[u].sh1) ----
    {
        const int el = tid >> 2, r = tid & 3;
        float s1x = sh1_s[el * 4 + 0], s1y = sh1_s[el * 4 + 1], s1z = sh1_s[el * 4 + 2];
#pragma unroll
        for (int q = 0; q < 4; ++q) {
            int u = r * 4 + q;
            float pv = v_sm[el * 49 + u * 3 + 0] * s1x
                     + v_sm[el * 49 + u * 3 + 1] * s1y
                     + v_sm[el * 49 + u * 3 + 2] * s1z;
            p_sm[el * 17 + u] = I3C * pv;
        }
    }
    __syncthreads();

    // ---- hoist h fragments (tile-invariant) into registers ----
    uint32_t aA = smb + SM_A
                + (uint32_t)(we * 16 + (lane & 15)) * 272 + (uint32_t)(lane >> 4) * 16;
    uint32_t af[8][4];
#pragma unroll
    for (int kk = 0; kk < 8; ++kk)
        ldsm4(aA + kk * 32, af[kk][0], af[kk][1], af[kk][2], af[kk][3]);

    uint32_t bBase = smb + SM_B + (uint32_t)wpar * 8704u + bOff;

    const float sh0a = sh0_s[ea],  sh0b = sh0_s[ebg];
    const float s1a0 = sh1_s[ea * 4 + 0], s1a1 = sh1_s[ea * 4 + 1], s1a2 = sh1_s[ea * 4 + 2];
    const float s1b0 = sh1_s[ebg * 4 + 0], s1b1 = sh1_s[ebg * 4 + 1], s1b2 = sh1_s[ebg * 4 + 2];

    float acc0a[8], acc0b[8];
    float acc1a[4][3], acc1b[4][3];
#pragma unroll
    for (int i = 0; i < 8; ++i) { acc0a[i] = 0.f; acc0b[i] = 0.f; }
#pragma unroll
    for (int j = 0; j < 4; ++j)
#pragma unroll
        for (int i = 0; i < 3; ++i) { acc1a[j][i] = 0.f; acc1b[j][i] = 0.f; }

    // ---- super-iteration loop: pair s (tiles 2s, 2s+1), 2-barrier double buffer ----
    for (int s = 0; s < NS; ++s) {
        if (s < NS - 1) CP_WAIT1(); else CP_WAIT0();
        __syncthreads();
        int t = 2 * s + wpar;
        tile_step(t, af, bBase + (uint32_t)(s & 1) * 17408u, ea, ebg, tg2,
                  s_sm, v_sm, p_sm, b2s,
                  sh0a, sh0b, s1a0, s1a1, s1a2, s1b0, s1b1, s1b2,
                  acc0a, acc0b, acc1a, acc1b);
        __syncthreads();
        if (s + 2 < NS) { load_pair(smb, s & 1, 2 * s + 4, tid); CP_COMMIT(); }
    }

    // ---- epilogue: scatter-add by src ----
    {
        int sa = edge_index[e0 + ea];
        int sb = edge_index[e0 + ebg];
        float* da = g_sums + (size_t)sa * DIMX;
        float* db = g_sums + (size_t)sb * DIMX;
#pragma unroll
        for (int i = 0; i < 8; ++i) {
            int wp = wpar * 32 + (i >> 1) * 8 + tg2 + (i & 1);
            atomicAdd(da + wp, N0C * acc0a[i]);
            atomicAdd(db + wp, N0C * acc0b[i]);
        }
#pragma unroll
        for (int j = 0; j < 4; ++j) {
            int wp = (j >> 1) * 8 + tg2 + (j & 1);
            atomicAdd(da + M0 + wp * 3 + 0, N1I * acc1a[j][0]);
            atomicAdd(da + M0 + wp * 3 + 1, N1I * acc1a[j][1]);
            atomicAdd(da + M0 + wp * 3 + 2, N1I * acc1a[j][2]);
            atomicAdd(db + M0 + wp * 3 + 0, N1I * acc1b[j][0]);
            atomicAdd(db + M0 + wp * 3 + 1, N1I * acc1b[j][1]);
            atomicAdd(db + M0 + wp * 3 + 2, N1I * acc1b[j][2]);
        }
    }
}

__global__ void finalize(const float* __restrict__ node_attr, float* __restrict__ out) {
    int i = blockIdx.x * blockDim.x + threadIdx.x;
    if (i >= NN * DIMX) return;
    int n = i / DIMX;
    float c = fmaxf(g_cnt[n], 1.0f);
    out[i] = g_sums[i] / c + node_attr[i];
}

extern "C" void kernel_launch(void* const* d_in, const int* in_sizes, int n_in,
                              void* d_out, int out_size) {
    const float* node_attr  = (const float*)d_in[0];
    const int*   edge_index = (const int*)  d_in[1];
    const float* edge_attr  = (const float*)d_in[2];
    const float* edge_sh    = (const float*)d_in[3];
    const float* W1         = (const float*)d_in[6];
    const float* b1         = (const float*)d_in[7];
    const float* W2         = (const float*)d_in[8];
    const float* b2         = (const float*)d_in[9];
    float* out = (float*)d_out;

    cudaFuncSetAttribute(tp_main, cudaFuncAttributeMaxDynamicSharedMemorySize, SM_TOTAL);

    prep<<<(EE * 128 + 255) / 256, 256>>>(W2, W1, edge_attr);
    tp_main<<<NBLK, 512, SM_TOTAL>>>(node_attr, edge_index, edge_attr,
                                     edge_sh, b1, b2);
    finalize<<<(NN * DIMX + 255) / 256, 256>>>(node_attr, out);
}

// round 17
// speedup vs baseline: 3.3990x; 1.0643x over previous
#include <cuda_runtime.h>
#include <cuda_fp16.h>
#include <cstdint>

// ---------------- problem constants ----------------
#define NN   4096
#define EE   32768
#define HIDD 128
#define M0   64
#define DIMX 112          // M0 + 3*16
#define WNUM 6400
#define NT   200          // 6400 / 32 column tiles
#define NS   100          // super-iterations (tile pairs)
#define TMB  128          // edges per block
#define NBLK (EE / TMB)   // 256

#define N0C  0.11180339887498948f   // sqrt(1/80)
#define N1C  0.19364916731037085f   // sqrt(3/80)
#define I3C  0.57735026918962576f   // 1/sqrt(3)
#define N1I  (N1C * I3C)

// ---------------- device scratch (no allocation allowed) ----------------
__device__ __half g_B[WNUM * HIDD];     // W2T fp16, [c][k] k-contiguous
__device__ __half g_W1h[HIDD * HIDD];   // W1T fp16, [c][j] j-contiguous
__device__ __half g_EA[EE * 128];       // edge_attr fp16
__device__ float g_sums[NN * DIMX];
__device__ float g_cnt[NN];

// ---------------- smem byte layout (109.5 KB -> 2 blocks/SM) ----------------
#define SSH  68              // s stride (halfs)
#define VSH  52              // v stride (halfs)
#define PSH  17              // p stride (floats)
#define SM_A    0            // h fp16 plane: 128 x 272 B = 34816
#define SM_B    34816        // 4 B slots x 8704 = 34816 (holds W1h during phase 3)
#define SM_UN   69632        // union { ea16 34816 | s16/v16/p 39424 }
#define SM_S    SM_UN                    // 128 x 68 half = 17408
#define SM_V    (SM_UN + 17408)          // 128 x 52 half = 13312
#define SM_P    (SM_UN + 30720)          // 128 x 17 f32  = 8704  (union end 39424)
#define SM_SH0  (SM_UN + 39424)          // 109056: 128 f32
#define SM_SH1  (SM_SH0 + 512)           // 109568: 128 x 4 f32
#define SM_B1S  (SM_SH1 + 2048)          // 111616: b1 128 f32
#define SM_TOTAL 112128

// ---------------- helpers ----------------
__device__ __forceinline__ uint32_t smem_u32(const void* p) {
    uint32_t a;
    asm("{ .reg .u64 t; cvta.to.shared.u64 t, %1; cvt.u32.u64 %0, t; }" : "=r"(a) : "l"(p));
    return a;
}
__device__ __forceinline__ void cp16(uint32_t dst, const void* src) {
    asm volatile("cp.async.cg.shared.global [%0], [%1], 16;" :: "r"(dst), "l"(src));
}
#define CP_COMMIT() asm volatile("cp.async.commit_group;" ::: "memory")
#define CP_WAIT1()  asm volatile("cp.async.wait_group 1;" ::: "memory")
#define CP_WAIT0()  asm volatile("cp.async.wait_group 0;" ::: "memory")

__device__ __forceinline__ void ldsm4(uint32_t addr, uint32_t& r0, uint32_t& r1,
                                      uint32_t& r2, uint32_t& r3) {
    asm volatile("ldmatrix.sync.aligned.m8n8.x4.shared.b16 {%0,%1,%2,%3}, [%4];"
                 : "=r"(r0), "=r"(r1), "=r"(r2), "=r"(r3) : "r"(addr));
}
__device__ __forceinline__ void mma16816(float* c, uint32_t a0, uint32_t a1,
                                         uint32_t a2, uint32_t a3,
                                         uint32_t b0, uint32_t b1) {
    asm volatile("mma.sync.aligned.m16n8k16.row.col.f32.f16.f16.f32 "
                 "{%0,%1,%2,%3}, {%4,%5,%6,%7}, {%8,%9}, {%0,%1,%2,%3};"
                 : "+f"(c[0]), "+f"(c[1]), "+f"(c[2]), "+f"(c[3])
                 : "r"(a0), "r"(a1), "r"(a2), "r"(a3), "r"(b0), "r"(b1));
}

// ---------------- single prep kernel (zero + all fp16 conversions) ----------------
__global__ void prep(const float* __restrict__ W2, const float* __restrict__ W1,
                     const float* __restrict__ EA) {
    int idx = blockIdx.x * blockDim.x + threadIdx.x;
    if (idx < EE * 128)
        g_EA[idx] = __float2half_rn(EA[idx]);
    if (idx < WNUM * HIDD) {
        int c = idx >> 7, k = idx & 127;
        g_B[idx] = __float2half_rn(W2[(size_t)k * WNUM + c]);
    }
    if (idx < HIDD * HIDD) {
        int c = idx >> 7, j = idx & 127;
        g_W1h[idx] = __float2half_rn(W1[j * HIDD + c]);
    }
    if (idx < NN * DIMX) g_sums[idx] = 0.0f;
    if (idx < NN)        g_cnt[idx]  = 0.0f;
}

// Stage a tile PAIR (tiles t, t+1) into pair slot p. 256 threads.
__device__ __forceinline__ void load_pair(uint32_t smb, int p, int t, int tid) {
    uint32_t base = smb + SM_B + (uint32_t)p * 17408u;
#pragma unroll
    for (int half = 0; half < 2; ++half) {
        uint32_t d = base + (uint32_t)half * 8704u;
        const char* src = (const char*)g_B + (size_t)(t + half) * 8192;
#pragma unroll
        for (int j = 0; j < 2; ++j) {
            int i = j * 256 + tid;
            int row = i >> 4, c = i & 15;
            cp16(d + row * 272 + c * 16, src + i * 16);
        }
    }
}

// ---------------- tile compute + consume (PAR = t&1, compile-time) ----------------
template<int PAR>
__device__ __forceinline__ void tile_step(
    int t, const uint32_t (&af)[8][4], uint32_t bA,
    int ea, int ebg, int tg2,
    const __half* __restrict__ s_h, const __half* __restrict__ v_h,
    const float* __restrict__ p_sm, const float* __restrict__ b2,
    float sh0a, float sh0b,
    float s1a0, float s1a1, float s1a2,
    float s1b0, float s1b1, float s1b2,
    float (&acc0a)[16], float (&acc0b)[16],
    float (&acc1a)[4][3], float (&acc1b)[4][3])
{
    float cf[4][4];
#pragma unroll
    for (int nt = 0; nt < 4; ++nt)
#pragma unroll
        for (int j = 0; j < 4; ++j) cf[nt][j] = 0.f;

#pragma unroll
    for (int kk = 0; kk < 8; ++kk) {
#pragma unroll
        for (int nt2 = 0; nt2 < 2; ++nt2) {
            uint32_t b0, b1, b2r, b3;
            ldsm4(bA + nt2 * 4352 + kk * 32, b0, b1, b2r, b3);
            mma16816(cf[nt2 * 2 + 0], af[kk][0], af[kk][1], af[kk][2], af[kk][3], b0, b1);
            mma16816(cf[nt2 * 2 + 1], af[kk][0], af[kk][1], af[kk][2], af[kk][3], b2r, b3);
        }
    }

    // add bias (direct LDG, L1/L2-hot)
    const float* b2t = b2 + t * 32;
#pragma unroll
    for (int nt = 0; nt < 4; ++nt) {
        float2 bb = *(const float2*)(b2t + nt * 8 + tg2);
        cf[nt][0] += bb.x; cf[nt][1] += bb.y;
        cf[nt][2] += bb.x; cf[nt][3] += bb.y;
    }

    if (t < 128) {                                 // region A: u = t>>1
        int u = t >> 1;
        float lfa = sh0a * __half2float(s_h[ea * SSH + u]);
        float lfb = sh0b * __half2float(s_h[ebg * SSH + u]);
#pragma unroll
        for (int nt = 0; nt < 4; ++nt) {
            acc0a[PAR * 8 + nt * 2 + 0] = fmaf(lfa, cf[nt][0], acc0a[PAR * 8 + nt * 2 + 0]);
            acc0a[PAR * 8 + nt * 2 + 1] = fmaf(lfa, cf[nt][1], acc0a[PAR * 8 + nt * 2 + 1]);
            acc0b[PAR * 8 + nt * 2 + 0] = fmaf(lfb, cf[nt][2], acc0b[PAR * 8 + nt * 2 + 0]);
            acc0b[PAR * 8 + nt * 2 + 1] = fmaf(lfb, cf[nt][3], acc0b[PAR * 8 + nt * 2 + 1]);
        }
    } else if (t < 160) {                          // region B
        int tb = 2 * (t - 128);
#pragma unroll
        for (int nt = 0; nt < 4; ++nt) {
            int u = tb + (nt >> 1);
            const int sl = (nt & 1) * 2;
            float sua = __half2float(s_h[ea * SSH + u]);
            float sub = __half2float(s_h[ebg * SSH + u]);
            float ta0 = sua * cf[nt][0], ta1 = sua * cf[nt][1];
            float tb0 = sub * cf[nt][2], tb1 = sub * cf[nt][3];
            acc1a[sl + 0][0] = fmaf(ta0, s1a0, acc1a[sl + 0][0]);
            acc1a[sl + 0][1] = fmaf(ta0, s1a1, acc1a[sl + 0][1]);
            acc1a[sl + 0][2] = fmaf(ta0, s1a2, acc1a[sl + 0][2]);
            acc1a[sl + 1][0] = fmaf(ta1, s1a0, acc1a[sl + 1][0]);
            acc1a[sl + 1][1] = fmaf(ta1, s1a1, acc1a[sl + 1][1]);
            acc1a[sl + 1][2] = fmaf(ta1, s1a2, acc1a[sl + 1][2]);
            acc1b[sl + 0][0] = fmaf(tb0, s1b0, acc1b[sl + 0][0]);
            acc1b[sl + 0][1] = fmaf(tb0, s1b1, acc1b[sl + 0][1]);
            acc1b[sl + 0][2] = fmaf(tb0, s1b2, acc1b[sl + 0][2]);
            acc1b[sl + 1][0] = fmaf(tb1, s1b0, acc1b[sl + 1][0]);
            acc1b[sl + 1][1] = fmaf(tb1, s1b1, acc1b[sl + 1][1]);
            acc1b[sl + 1][2] = fmaf(tb1, s1b2, acc1b[sl + 1][2]);
        }
    } else if (t < 168) {                          // region C
        int tb = 2 * (t - 160);
#pragma unroll
        for (int nt = 0; nt < 4; ++nt) {
            int u = tb + (nt >> 1);
            const int sl = (nt & 1) * 2;
            float twa0 = sh0a * cf[nt][0], twa1 = sh0a * cf[nt][1];
            float twb0 = sh0b * cf[nt][2], twb1 = sh0b * cf[nt][3];
            float va0 = __half2float(v_h[ea * VSH + u * 3 + 0]);
            float va1 = __half2float(v_h[ea * VSH + u * 3 + 1]);
            float va2 = __half2float(v_h[ea * VSH + u * 3 + 2]);
            float vb0 = __half2float(v_h[ebg * VSH + u * 3 + 0]);
            float vb1 = __half2float(v_h[ebg * VSH + u * 3 + 1]);
            float vb2 = __half2float(v_h[ebg * VSH + u * 3 + 2]);
            acc1a[sl + 0][0] = fmaf(twa0, va0, acc1a[sl + 0][0]);
            acc1a[sl + 0][1] = fmaf(twa0, va1, acc1a[sl + 0][1]);
            acc1a[sl + 0][2] = fmaf(twa0, va2, acc1a[sl + 0][2]);
            acc1a[sl + 1][0] = fmaf(twa1, va0, acc1a[sl + 1][0]);
            acc1a[sl + 1][1] = fmaf(twa1, va1, acc1a[sl + 1][1]);
            acc1a[sl + 1][2] = fmaf(twa1, va2, acc1a[sl + 1][2]);
            acc1b[sl + 0][0] = fmaf(twb0, vb0, acc1b[sl + 0][0]);
            acc1b[sl + 0][1] = fmaf(twb0, vb1, acc1b[sl + 0][1]);
            acc1b[sl + 0][2] = fmaf(twb0, vb2, acc1b[sl + 0][2]);
            acc1b[sl + 1][0] = fmaf(twb1, vb0, acc1b[sl + 1][0]);
            acc1b[sl + 1][1] = fmaf(twb1, vb1, acc1b[sl + 1][1]);
            acc1b[sl + 1][2] = fmaf(twb1, vb2, acc1b[sl + 1][2]);
        }
    } else {                                       // region D: u = (t-168)>>1
        int u = (t - 168) >> 1;
        float lfa = p_sm[ea * PSH + u];
        float lfb = p_sm[ebg * PSH + u];
#pragma unroll
        for (int nt = 0; nt < 4; ++nt) {
            acc0a[PAR * 8 + nt * 2 + 0] = fmaf(lfa, cf[nt][0], acc0a[PAR * 8 + nt * 2 + 0]);
            acc0a[PAR * 8 + nt * 2 + 1] = fmaf(lfa, cf[nt][1], acc0a[PAR * 8 + nt * 2 + 1]);
            acc0b[PAR * 8 + nt * 2 + 0] = fmaf(lfb, cf[nt][2], acc0b[PAR * 8 + nt * 2 + 0]);
            acc0b[PAR * 8 + nt * 2 + 1] = fmaf(lfb, cf[nt][3], acc0b[PAR * 8 + nt * 2 + 1]);
        }
    }
}

// ---------------- main fused kernel (256 threads, 2 blocks/SM) ----------------
__global__ __launch_bounds__(256, 2)
void tp_main(const float* __restrict__ node_attr,
             const int*   __restrict__ edge_index,
             const float* __restrict__ edge_sh,
             const float* __restrict__ b1,
             const float* __restrict__ b2)
{
    extern __shared__ char smc[];
    const uint32_t smb = smem_u32(smc);
    const int tid = threadIdx.x;
    const int e0  = blockIdx.x * TMB;

    float* sh0_s = (float*)(smc + SM_SH0);
    float* sh1_s = (float*)(smc + SM_SH1);
    __half* s_h  = (__half*)(smc + SM_S);
    __half* v_h  = (__half*)(smc + SM_V);
    float* p_sm  = (float*)(smc + SM_P);
    float* b1s   = (float*)(smc + SM_B1S);

    // ---- lane/warp decomposition ----
    const int lane = tid & 31;
    const int w    = tid >> 5;       // 0..7 (edge group)
    const int g    = lane >> 2;
    const int tg2  = (lane & 3) * 2;
    const int ea   = w * 16 + g;
    const int ebg  = ea + 8;
    uint32_t bOff = (uint32_t)((lane >> 4) & 1) * (8u * 272u)
                  + (uint32_t)(lane & 7) * 272u
                  + (uint32_t)((lane >> 3) & 1) * 16u;

    // ---- prologue cp.async group0: b1 + ea16(->UN) + W1h(->B region) ----
    if (tid < 32)
        cp16(smb + SM_B1S + tid * 16, b1 + tid * 4);
#pragma unroll
    for (int j = 0; j < 8; ++j) {                   // ea16: 2048 chunks
        int i = j * 256 + tid;
        int row = i >> 4, c = i & 15;
        cp16(smb + SM_UN + row * 272 + c * 16,
             (const char*)g_EA + (size_t)e0 * 256 + (size_t)i * 16);
    }
#pragma unroll
    for (int j = 0; j < 8; ++j) {                   // W1h: 2048 chunks -> SM_B
        int i = j * 256 + tid;
        int row = i >> 4, c = i & 15;
        cp16(smb + SM_B + row * 272 + c * 16, (const char*)g_W1h + (size_t)i * 16);
    }
    CP_COMMIT();

    // ---- phase 1: edge_sh + counts ----
    if (tid < TMB) {
        int e = e0 + tid;
        float4 shv = *(const float4*)(edge_sh + (size_t)e * 4);
        sh0_s[tid] = shv.x;
        sh1_s[tid * 4 + 0] = shv.y;
        sh1_s[tid * 4 + 1] = shv.z;
        sh1_s[tid * 4 + 2] = shv.w;
        atomicAdd(&g_cnt[edge_index[e]], 1.0f);
    }

    CP_WAIT0();
    __syncthreads();

    // ---- phase 3: h = relu(ea@W1+b1) via MMA -> fp16 A plane ----
    {
        uint32_t aE = smb + SM_UN
                    + (uint32_t)(w * 16 + (lane & 15)) * 272 + (uint32_t)(lane >> 4) * 16;
        uint32_t ef[8][4];
#pragma unroll
        for (int kk = 0; kk < 8; ++kk)
            ldsm4(aE + kk * 32, ef[kk][0], ef[kk][1], ef[kk][2], ef[kk][3]);

        uint32_t bW = smb + SM_B + bOff;
#pragma unroll
        for (int grp = 0; grp < 4; ++grp) {
            float cf[4][4];
#pragma unroll
            for (int nt = 0; nt < 4; ++nt)
#pragma unroll
                for (int j = 0; j < 4; ++j) cf[nt][j] = 0.f;
#pragma unroll
            for (int kk = 0; kk < 8; ++kk) {
#pragma unroll
                for (int nt2 = 0; nt2 < 2; ++nt2) {
                    uint32_t b0, b1r, b2r, b3;
                    ldsm4(bW + grp * 8704u + nt2 * 4352 + kk * 32, b0, b1r, b2r, b3);
                    mma16816(cf[nt2 * 2 + 0], ef[kk][0], ef[kk][1], ef[kk][2], ef[kk][3], b0, b1r);
                    mma16816(cf[nt2 * 2 + 1], ef[kk][0], ef[kk][1], ef[kk][2], ef[kk][3], b2r, b3);
                }
            }
#pragma unroll
            for (int nt = 0; nt < 4; ++nt) {
                int c0 = grp * 32 + nt * 8 + tg2;
                float bb0 = b1s[c0], bb1 = b1s[c0 + 1];
                __half2 h0 = __floats2half2_rn(fmaxf(cf[nt][0] + bb0, 0.f),
                                               fmaxf(cf[nt][1] + bb1, 0.f));
                __half2 h1 = __floats2half2_rn(fmaxf(cf[nt][2] + bb0, 0.f),
                                               fmaxf(cf[nt][3] + bb1, 0.f));
                *(__half2*)(smc + SM_A + (w * 16 + g) * 272 + c0 * 2) = h0;
                *(__half2*)(smc + SM_A + (w * 16 + g + 8) * 272 + c0 * 2) = h1;
            }
        }
    }
    __syncthreads();   // phase-3 reads of ea16/W1h done; h stores visible

    // ---- B pipeline start (overwrites W1h region) ----
    load_pair(smb, 0, 0, tid);
    CP_COMMIT();
    load_pair(smb, 1, 2, tid);
    CP_COMMIT();

    // ---- phase 4: gather node_attr[dst] -> s/v fp16 (overwrites ea16) ----
    {
        const int el = tid >> 1, r = tid & 1;
        int dstn = edge_index[EE + e0 + el];
        const float4* nb = (const float4*)(node_attr + (size_t)dstn * DIMX);
#pragma unroll
        for (int tt = 0; tt < 14; ++tt) {
            int f4 = r * 14 + tt;
            float4 v = nb[f4];
            int col = f4 * 4;
            if (col < M0) {
                *(__half2*)(s_h + el * SSH + col)     = __floats2half2_rn(v.x, v.y);
                *(__half2*)(s_h + el * SSH + col + 2) = __floats2half2_rn(v.z, v.w);
            } else {
                int q = col - M0;
                *(__half2*)(v_h + el * VSH + q)     = __floats2half2_rn(v.x, v.y);
                *(__half2*)(v_h + el * VSH + q + 2) = __floats2half2_rn(v.z, v.w);
            }
        }
    }
    __syncthreads();

    // ---- phase 5: p[u] = I3C * (v[u].sh1) ----
    {
        const int el = tid >> 1, r = tid & 1;
        float s1x = sh1_s[el * 4 + 0], s1y = sh1_s[el * 4 + 1], s1z = sh1_s[el * 4 + 2];
#pragma unroll
        for (int q = 0; q < 8; ++q) {
            int u = r * 8 + q;
            float pv = __half2float(v_h[el * VSH + u * 3 + 0]) * s1x
                     + __half2float(v_h[el * VSH + u * 3 + 1]) * s1y
                     + __half2float(v_h[el * VSH + u * 3 + 2]) * s1z;
            p_sm[el * PSH + u] = I3C * pv;
        }
    }
    __syncthreads();

    // ---- hoist h fragments (tile-invariant) into registers ----
    uint32_t aA = smb + SM_A
                + (uint32_t)(w * 16 + (lane & 15)) * 272 + (uint32_t)(lane >> 4) * 16;
    uint32_t af[8][4];
#pragma unroll
    for (int kk = 0; kk < 8; ++kk)
        ldsm4(aA + kk * 32, af[kk][0], af[kk][1], af[kk][2], af[kk][3]);

    uint32_t bBase = smb + SM_B + bOff;

    const float sh0a = sh0_s[ea],  sh0b = sh0_s[ebg];
    const float s1a0 = sh1_s[ea * 4 + 0], s1a1 = sh1_s[ea * 4 + 1], s1a2 = sh1_s[ea * 4 + 2];
    const float s1b0 = sh1_s[ebg * 4 + 0], s1b1 = sh1_s[ebg * 4 + 1], s1b2 = sh1_s[ebg * 4 + 2];

    float acc0a[16], acc0b[16];
    float acc1a[4][3], acc1b[4][3];
#pragma unroll
    for (int i = 0; i < 16; ++i) { acc0a[i] = 0.f; acc0b[i] = 0.f; }
#pragma unroll
    for (int j = 0; j < 4; ++j)
#pragma unroll
        for (int i = 0; i < 3; ++i) { acc1a[j][i] = 0.f; acc1b[j][i] = 0.f; }

    // ---- super-iteration loop: each warp does BOTH parities of pair s ----
    for (int s = 0; s < NS; ++s) {
        if (s < NS - 1) CP_WAIT1(); else CP_WAIT0();
        __syncthreads();
        uint32_t bp = bBase + (uint32_t)(s & 1) * 17408u;
        tile_step<0>(2 * s, af, bp, ea, ebg, tg2,
                     s_h, v_h, p_sm, b2,
                     sh0a, sh0b, s1a0, s1a1, s1a2, s1b0, s1b1, s1b2,
                     acc0a, acc0b, acc1a, acc1b);
        tile_step<1>(2 * s + 1, af, bp + 8704u, ea, ebg, tg2,
                     s_h, v_h, p_sm, b2,
                     sh0a, sh0b, s1a0, s1a1, s1a2, s1b0, s1b1, s1b2,
                     acc0a, acc0b, acc1a, acc1b);
        __syncthreads();
        if (s + 2 < NS) { load_pair(smb, s & 1, 2 * s + 4, tid); CP_COMMIT(); }
    }

    // ---- epilogue: scatter-add by src (R8-proven mapping) ----
    {
        int sa = edge_index[e0 + ea];
        int sb = edge_index[e0 + ebg];
        float* da = g_sums + (size_t)sa * DIMX;
        float* db = g_sums + (size_t)sb * DIMX;
#pragma unroll
        for (int i = 0; i < 16; ++i) {
            int wp = (i >> 3) * 32 + ((i >> 1) & 3) * 8 + tg2 + (i & 1);
            atomicAdd(da + wp, N0C * acc0a[i]);
            atomicAdd(db + wp, N0C * acc0b[i]);
        }
#pragma unroll
        for (int j = 0; j < 4; ++j) {
            int wp = (j >> 1) * 8 + tg2 + (j & 1);
            atomicAdd(da + M0 + wp * 3 + 0, N1I * acc1a[j][0]);
            atomicAdd(da + M0 + wp * 3 + 1, N1I * acc1a[j][1]);
            atomicAdd(da + M0 + wp * 3 + 2, N1I * acc1a[j][2]);
            atomicAdd(db + M0 + wp * 3 + 0, N1I * acc1b[j][0]);
            atomicAdd(db + M0 + wp * 3 + 1, N1I * acc1b[j][1]);
            atomicAdd(db + M0 + wp * 3 + 2, N1I * acc1b[j][2]);
        }
    }
}

__global__ void finalize(const float* __restrict__ node_attr, float* __restrict__ out) {
    int i = blockIdx.x * blockDim.x + threadIdx.x;
    if (i >= NN * DIMX) return;
    int n = i / DIMX;
    float c = fmaxf(g_cnt[n], 1.0f);
    out[i] = g_sums[i] / c + node_attr[i];
}

extern "C" void kernel_launch(void* const* d_in, const int* in_sizes, int n_in,
                              void* d_out, int out_size) {
    const float* node_attr  = (const float*)d_in[0];
    const int*   edge_index = (const int*)  d_in[1];
    const float* edge_attr  = (const float*)d_in[2];
    const float* edge_sh    = (const float*)d_in[3];
    const float* W1         = (const float*)d_in[6];
    const float* b1         = (const float*)d_in[7];
    const float* W2         = (const float*)d_in[8];
    const float* b2         = (const float*)d_in[9];
    float* out = (float*)d_out;

    cudaFuncSetAttribute(tp_main, cudaFuncAttributeMaxDynamicSharedMemorySize, SM_TOTAL);

    prep<<<(EE * 128 + 255) / 256, 256>>>(W2, W1, edge_attr);
    tp_main<<<NBLK, 256, SM_TOTAL>>>(node_attr, edge_index, edge_sh, b1, b2);
    finalize<<<(NN * DIMX + 255) / 256, 256>>>(node_attr, out);
}